// round 3
// baseline (speedup 1.0000x reference)
#include <cuda_runtime.h>
#include <cuda_bf16.h>
#include <cstdint>

// problem constants
#define CC   96
#define LL   2304            // 48*48
#define NBQ  64              // 4 quads * 16 batch
#define PXQ  36864           // 16*2304 pixels per quadrant
#define XDW  24              // padded record: dts[6],pad[2],B[8],C[8]

// ---------------- static scratch ----------------
__device__ float g_hln [NBQ*LL*CC];
__device__ float g_a   [NBQ*LL*CC];
__device__ float g_zin [NBQ*LL*CC];
__device__ float g_vf  [NBQ*LL*CC];
__device__ float g_vt  [NBQ*LL*CC];
__device__ float g_xdbl[NBQ*4*LL*XDW];
__device__ float g_ys  [NBQ*4*LL*CC];
__device__ float g_y   [NBQ*LL*CC];
__device__ float g_ysum[NBQ*CC];
__device__ float g_att [NBQ*CC];

__device__ __forceinline__ float siluf(float v){ return v * (1.f/(1.f+__expf(-v))); }

__device__ __forceinline__ void fma2(unsigned long long &acc, unsigned long long a, unsigned long long b){
    asm("fma.rn.f32x2 %0,%1,%2,%0;" : "+l"(acc) : "l"(a), "l"(b));
}
__device__ __forceinline__ unsigned long long pack2(float v){
    unsigned long long r; asm("mov.b64 %0,{%1,%1};" : "=l"(r) : "f"(v)); return r;
}
__device__ __forceinline__ float2 unpack2(unsigned long long v){
    float2 r; asm("mov.b64 {%0,%1},%2;" : "=f"(r.x), "=f"(r.y) : "l"(v)); return r;
}
__device__ __forceinline__ void cpasync16(void* dst, const void* src){
    unsigned d = (unsigned)__cvta_generic_to_shared(dst);
    asm volatile("cp.async.ca.shared.global [%0],[%1],16;" :: "r"(d), "l"(src));
}

// =============== K0: channel LN of x -> g_hln (pixel-major) ===============
__global__ __launch_bounds__(256) void k0_ln(const float* __restrict__ x,
                                             const float* __restrict__ lg,
                                             const float* __restrict__ lb)
{
    __shared__ float tile[96*49];
    __shared__ float mu_s[48], rs_s[48];
    int qb = blockIdx.x, q = qb>>4, bb = qb&15, hr = blockIdx.y;
    if (blockIdx.x==0 && blockIdx.y==0)
        for (int i=threadIdx.x; i<NBQ*CC; i+=256) g_ysum[i]=0.f;
    int qh=(q>>1)*48, qw=(q&1)*48;
    const float* xb = x + (size_t)bb*96*96*96 + (size_t)(qh+hr)*96 + qw;
    for (int i=threadIdx.x; i<96*48; i+=256){
        int c=i/48, w=i%48;
        tile[c*49+w] = xb[(size_t)c*9216 + w];
    }
    __syncthreads();
    if (threadIdx.x < 48){
        int w=threadIdx.x; float s=0.f, ss=0.f;
        #pragma unroll 8
        for (int c=0;c<96;c++){ float v=tile[c*49+w]; s+=v; ss+=v*v; }
        float m=s*(1.f/96.f); float var=ss*(1.f/96.f)-m*m;
        mu_s[w]=m; rs_s[w]=rsqrtf(var+1e-6f);
    }
    __syncthreads();
    const float* gg=lg+q*96; const float* bv=lb+q*96;
    float* out = g_hln + ((size_t)qb*LL + hr*48)*96;
    for (int i=threadIdx.x; i<48*96; i+=256){
        int w=i/96, c=i%96;
        out[i] = (tile[c*49+w]-mu_s[w])*rs_s[w]*gg[c] + bv[c];
    }
}

// =============== K1: both 1x1 convs fused, register-tiled FFMA2 GEMM ===============
// grid (288, 4), block 256 = 16 tp x 16 tc. Tile: 128 px x 192 oc.
// Thread: 8 px (4 f32x2 pairs) x 12 oc (6 per conv).
#define K1XS 132
#define K1WS 194
__global__ __launch_bounds__(256) void k1_gemm(const float* __restrict__ p1w, const float* __restrict__ p1b,
                                               const float* __restrict__ p2w, const float* __restrict__ p2b)
{
    extern __shared__ float sm[];
    float* Xs = sm;                 // [96][132]
    float* Ws = sm + 96*K1XS;       // [96][194] : conv0 oc 0..95, conv1 oc 96..191
    int q = blockIdx.y, P0 = blockIdx.x*128;
    const float* base = g_hln + ((size_t)q*PXQ + P0)*96;
    for (int i=threadIdx.x; i<128*96; i+=256){ int p=i/96, c=i%96; Xs[c*K1XS+p] = base[i]; }
    const float* W0 = p1w + (size_t)q*9216;
    const float* W1 = p2w + (size_t)q*9216;
    for (int i=threadIdx.x; i<9216; i+=256){
        int d=i/96, c=i%96;
        Ws[c*K1WS+d]    = W0[i];
        Ws[c*K1WS+96+d] = W1[i];
    }
    __syncthreads();
    int tp = threadIdx.x & 15, tc = threadIdx.x >> 4;
    unsigned long long acc[12][4];
    #pragma unroll
    for (int j=0;j<12;j++){ acc[j][0]=0ull; acc[j][1]=0ull; acc[j][2]=0ull; acc[j][3]=0ull; }
    const float* xb = Xs + 8*tp;
    const float* wb = Ws + tc*6;
    #pragma unroll 2
    for (int k=0;k<96;k++){
        ulonglong2 x0 = *(const ulonglong2*)(xb + k*K1XS);
        ulonglong2 x1 = *(const ulonglong2*)(xb + k*K1XS + 4);
        const float* wr = wb + k*K1WS;
        float2 a0 = *(const float2*)(wr);
        float2 a1 = *(const float2*)(wr+2);
        float2 a2 = *(const float2*)(wr+4);
        float2 a3 = *(const float2*)(wr+96);
        float2 a4 = *(const float2*)(wr+98);
        float2 a5 = *(const float2*)(wr+100);
        float wf[12] = {a0.x,a0.y,a1.x,a1.y,a2.x,a2.y, a3.x,a3.y,a4.x,a4.y,a5.x,a5.y};
        #pragma unroll
        for (int j=0;j<12;j++){
            unsigned long long wv = pack2(wf[j]);
            fma2(acc[j][0], x0.x, wv);
            fma2(acc[j][1], x0.y, wv);
            fma2(acc[j][2], x1.x, wv);
            fma2(acc[j][3], x1.y, wv);
        }
    }
    float bs0[6], bs1[6];
    #pragma unroll
    for (int j=0;j<6;j++){ bs0[j]=p1b[q*96+tc*6+j]; bs1[j]=p2b[q*96+tc*6+j]; }
    #pragma unroll
    for (int i=0;i<4;i++){
        float2 v[12];
        #pragma unroll
        for (int j=0;j<12;j++) v[j]=unpack2(acc[j][i]);
        size_t pbase = ((size_t)q*PXQ + P0 + 8*tp + 2*i)*96 + tc*6;
        // conv0 (silu) -> g_a, two pixels
        #pragma unroll
        for (int h=0; h<2; h++){
            float r0 = siluf((h? v[0].y : v[0].x)+bs0[0]);
            float r1 = siluf((h? v[1].y : v[1].x)+bs0[1]);
            float r2 = siluf((h? v[2].y : v[2].x)+bs0[2]);
            float r3 = siluf((h? v[3].y : v[3].x)+bs0[3]);
            float r4 = siluf((h? v[4].y : v[4].x)+bs0[4]);
            float r5 = siluf((h? v[5].y : v[5].x)+bs0[5]);
            float* da = g_a + pbase + h*96;
            *(float2*)(da)   = make_float2(r0,r1);
            *(float2*)(da+2) = make_float2(r2,r3);
            *(float2*)(da+4) = make_float2(r4,r5);
            float s0 = (h? v[6].y  : v[6].x )+bs1[0];
            float s1 = (h? v[7].y  : v[7].x )+bs1[1];
            float s2 = (h? v[8].y  : v[8].x )+bs1[2];
            float s3 = (h? v[9].y  : v[9].x )+bs1[3];
            float s4 = (h? v[10].y : v[10].x)+bs1[4];
            float s5 = (h? v[11].y : v[11].x)+bs1[5];
            float* dz = g_zin + pbase + h*96;
            *(float2*)(dz)   = make_float2(s0,s1);
            *(float2*)(dz+2) = make_float2(s2,s3);
            *(float2*)(dz+4) = make_float2(s4,s5);
        }
    }
}

// =============== K2: depthwise 3x3 + bias + silu + pre-transform ===============
__global__ __launch_bounds__(256) void k2_dw(const float* __restrict__ dww, const float* __restrict__ dwb,
                                             const int* __restrict__ bidx)
{
    extern __shared__ float rows[];         // [3][48*96]
    __shared__ float wsm[96*9];
    __shared__ float bsm[96];
    int qb = blockIdx.x, q = qb>>4, hr = blockIdx.y;
    for (int i=threadIdx.x; i<96*9; i+=256) wsm[i]=dww[q*96*9 + i];
    for (int i=threadIdx.x; i<96;   i+=256) bsm[i]=dwb[q*96 + i];
    for (int dy=0; dy<3; dy++){
        int hh = hr-1+dy;
        if (hh>=0 && hh<48){
            const float* src = g_zin + ((size_t)qb*LL + hh*48)*96;
            for (int i=threadIdx.x; i<48*96; i+=256) rows[dy*4608+i]=src[i];
        } else {
            for (int i=threadIdx.x; i<48*96; i+=256) rows[dy*4608+i]=0.f;
        }
    }
    __syncthreads();
    bool even = ((bidx[0] & 1) == 0);
    for (int i=threadIdx.x; i<48*96; i+=256){
        int w=i/96, c=i%96;
        float acc = bsm[c];
        #pragma unroll
        for (int dy=0; dy<3; dy++){
            #pragma unroll
            for (int dx=0; dx<3; dx++){
                int ww = w+dx-1;
                if (ww>=0 && ww<48) acc += wsm[c*9+dy*3+dx]*rows[dy*4608 + ww*96 + c];
            }
        }
        float z = siluf(acc);
        int pf, pt;
        if (even){ pf = w*48+hr;           pt = hr*48+w; }
        else     { pf = (47-hr)*48+(47-w); pt = (47-w)*48+(47-hr); }
        g_vf[((size_t)qb*LL + pf)*96 + c] = z;
        g_vt[((size_t)qb*LL + pt)*96 + c] = z;
    }
}

// =============== K3: x-projection GEMM, register-tiled ===============
// grid (144, 2, 4), block 256 = 16 tp x 16 tc. Tile: 256 px x 48 oc (44 real).
// Thread: 16 px (8 pairs) x 3 oc.
#define K3XS 260
#define K3WS 50
__global__ __launch_bounds__(256) void k3_proj(const float* __restrict__ xprojw)
{
    extern __shared__ float sm[];
    float* Xs = sm;                // [96][260]
    float* Ws = sm + 96*K3XS;      // [96][50]
    int q = blockIdx.z, src = blockIdx.y, P0 = blockIdx.x*256;
    const float* base = (src? g_vt : g_vf) + ((size_t)q*PXQ + P0)*96;
    for (int i=threadIdx.x; i<256*96; i+=256){ int p=i/96, c=i%96; Xs[c*K3XS+p]=base[i]; }
    for (int i=threadIdx.x; i<48*96; i+=256){
        int oc=i/96, kk=i%96;
        float v=0.f;
        if (oc<44){
            int k = (oc<22)? src : src+2;
            int d = (oc<22)? oc : oc-22;
            v = xprojw[(((size_t)q*4 + k)*22 + d)*96 + kk];
        }
        Ws[kk*K3WS+oc]=v;
    }
    __syncthreads();
    int tp = threadIdx.x & 15, tc = threadIdx.x >> 4;
    unsigned long long acc[3][8];
    #pragma unroll
    for (int j=0;j<3;j++)
        #pragma unroll
        for (int i=0;i<8;i++) acc[j][i]=0ull;
    const float* xb = Xs + 16*tp;
    const float* wb = Ws + tc*3;
    #pragma unroll 2
    for (int k=0;k<96;k++){
        ulonglong2 x0 = *(const ulonglong2*)(xb + k*K3XS);
        ulonglong2 x1 = *(const ulonglong2*)(xb + k*K3XS + 4);
        ulonglong2 x2 = *(const ulonglong2*)(xb + k*K3XS + 8);
        ulonglong2 x3 = *(const ulonglong2*)(xb + k*K3XS + 12);
        const float* wr = wb + k*K3WS;
        #pragma unroll
        for (int j=0;j<3;j++){
            unsigned long long wv = pack2(wr[j]);
            fma2(acc[j][0], x0.x, wv);
            fma2(acc[j][1], x0.y, wv);
            fma2(acc[j][2], x1.x, wv);
            fma2(acc[j][3], x1.y, wv);
            fma2(acc[j][4], x2.x, wv);
            fma2(acc[j][5], x2.y, wv);
            fma2(acc[j][6], x3.x, wv);
            fma2(acc[j][7], x3.y, wv);
        }
    }
    int b = P0 / LL;
    int l0 = P0 % LL + 16*tp;
    int qb = q*16 + b;
    #pragma unroll
    for (int j=0;j<3;j++){
        int oc = tc*3+j;
        if (oc>=44) continue;
        int k = (oc<22)? src : src+2;
        int d = (oc<22)? oc : oc-22;
        int pos = (d<6)? d : d+2;
        float* dst = g_xdbl + (((size_t)qb*4 + k)*LL + l0)*XDW + pos;
        #pragma unroll
        for (int i=0;i<8;i++){
            float2 v = unpack2(acc[j][i]);
            dst[(2*i  )*XDW] = v.x;
            dst[(2*i+1)*XDW] = v.y;
        }
    }
}

// =============== K-scan: selective scan, 1 thread per (q,b,k,c) lane ===============
__global__ __launch_bounds__(96) void k_scan(const float* __restrict__ dtw_g, const float* __restrict__ dtb_g,
                                             const float* __restrict__ alog_g, const float* __restrict__ ds_g)
{
    __shared__ float s_u [2][16*96];
    __shared__ float s_xd[2][16*XDW];
    int qb = blockIdx.x, k = blockIdx.y, q = qb>>4;
    int c = threadIdx.x;
    int pidx = (q*4+k)*96 + c;
    float dtw[6];
    #pragma unroll
    for (int r=0;r<6;r++) dtw[r]=dtw_g[pidx*6+r];
    float dtb = dtb_g[pidx];
    float Ac[8];
    #pragma unroll
    for (int n=0;n<8;n++) Ac[n] = -__expf(alog_g[pidx*8+n]);
    float Dv = ds_g[pidx];
    const float* u_base  = ((k&1)? g_vt : g_vf) + (size_t)qb*LL*96;
    const float* xd_base = g_xdbl + ((size_t)qb*4+k)*LL*XDW;
    float* ys_base = g_ys + ((size_t)qb*4+k)*LL*96;
    bool rev = (k>=2);
    float hs[8];
    #pragma unroll
    for (int n=0;n<8;n++) hs[n]=0.f;
    {
        int sst = rev ? (LL-16) : 0;
        const float4* us = (const float4*)(u_base + (size_t)sst*96);
        #pragma unroll
        for (int j=0;j<4;j++) cpasync16(&s_u[0][(j*96+c)*4], &us[j*96+c]);
        cpasync16(&s_xd[0][c*4], (const float4*)(xd_base + (size_t)sst*XDW) + c);
        asm volatile("cp.async.commit_group;");
    }
    for (int cs=0; cs<144; cs++){
        if (cs<143){
            int cn = cs+1;
            int sst = rev ? (LL - 16*(cn+1)) : 16*cn;
            int buf = cn & 1;
            const float4* us = (const float4*)(u_base + (size_t)sst*96);
            #pragma unroll
            for (int j=0;j<4;j++) cpasync16(&s_u[buf][(j*96+c)*4], &us[j*96+c]);
            cpasync16(&s_xd[buf][c*4], (const float4*)(xd_base + (size_t)sst*XDW) + c);
            asm volatile("cp.async.commit_group;");
            asm volatile("cp.async.wait_group 1;");
        } else {
            asm volatile("cp.async.wait_group 0;");
        }
        __syncthreads();
        int buf = cs & 1;
        int sst = rev ? (LL - 16*(cs+1)) : 16*cs;
        #pragma unroll 4
        for (int j=0;j<16;j++){
            int off = rev ? (15-j) : j;
            const float* xd = &s_xd[buf][off*XDW];
            float4 d4 = *(const float4*)xd;
            float2 d2 = *(const float2*)(xd+4);
            float draw = dtb + dtw[0]*d4.x + dtw[1]*d4.y + dtw[2]*d4.z + dtw[3]*d4.w
                             + dtw[4]*d2.x + dtw[5]*d2.y;
            float delta = (draw > 15.f) ? draw : __logf(1.f + __expf(draw));
            float u = s_u[buf][off*96 + c];
            float du = delta*u;
            float4 B0 = *(const float4*)(xd+8);
            float4 B1 = *(const float4*)(xd+12);
            float4 C0 = *(const float4*)(xd+16);
            float4 C1 = *(const float4*)(xd+20);
            float y = Dv*u;
            hs[0] = __expf(delta*Ac[0])*hs[0] + du*B0.x;  y += hs[0]*C0.x;
            hs[1] = __expf(delta*Ac[1])*hs[1] + du*B0.y;  y += hs[1]*C0.y;
            hs[2] = __expf(delta*Ac[2])*hs[2] + du*B0.z;  y += hs[2]*C0.z;
            hs[3] = __expf(delta*Ac[3])*hs[3] + du*B0.w;  y += hs[3]*C0.w;
            hs[4] = __expf(delta*Ac[4])*hs[4] + du*B1.x;  y += hs[4]*C1.x;
            hs[5] = __expf(delta*Ac[5])*hs[5] + du*B1.y;  y += hs[5]*C1.y;
            hs[6] = __expf(delta*Ac[6])*hs[6] + du*B1.z;  y += hs[6]*C1.z;
            hs[7] = __expf(delta*Ac[7])*hs[7] + du*B1.w;  y += hs[7]*C1.w;
            ys_base[(size_t)(sst+off)*96 + c] = y;
        }
        __syncthreads();
    }
}

// =============== K4: combine 4 dirs + ssln LN + p2n LN + a*z + ysum ===============
// grid (64, 48), block 96
__global__ __launch_bounds__(96) void k4_comb(const float* __restrict__ g1g, const float* __restrict__ b1g,
                                              const float* __restrict__ g2g, const float* __restrict__ b2g,
                                              const int* __restrict__ bidx)
{
    __shared__ float T[48*97];
    __shared__ float mu1[48], rs1[48], mu2[48], rs2[48];
    __shared__ float G1[96], B1[96], G2[96], B2[96];
    int qb = blockIdx.x, q = qb>>4, hr = blockIdx.y, tid = threadIdx.x;
    bool even = ((bidx[0] & 1) == 0);
    G1[tid]=g1g[q*96+tid]; B1[tid]=b1g[q*96+tid];
    G2[tid]=g2g[q*96+tid]; B2[tid]=b2g[q*96+tid];
    size_t ysq = (size_t)qb*4;
    const float* y0 = g_ys + (ysq+0)*LL*96;
    const float* y1 = g_ys + (ysq+1)*LL*96;
    const float* y2 = g_ys + (ysq+2)*LL*96;
    const float* y3 = g_ys + (ysq+3)*LL*96;
    for (int i=tid; i<48*96; i+=96){
        int w=i/96, c=i%96;
        int lf=hr*48+w, lt=w*48+hr;
        T[w*97+c] = y0[(size_t)lf*96+c] + y2[(size_t)lf*96+c]
                  + y1[(size_t)lt*96+c] + y3[(size_t)lt*96+c];
    }
    __syncthreads();
    {   // pass 1: raw stats
        int p = tid>>1, half = tid&1;
        float s=0.f, ss=0.f;
        const float* row = &T[p*97 + half*48];
        #pragma unroll 8
        for (int c=0;c<48;c++){ float v=row[c]; s+=v; ss+=v*v; }
        s  += __shfl_xor_sync(0xffffffffu, s, 1);
        ss += __shfl_xor_sync(0xffffffffu, ss, 1);
        if (half==0){
            float m = s*(1.f/96.f);
            mu1[p]=m; rs1[p]=rsqrtf(ss*(1.f/96.f)-m*m+1e-6f);
        }
    }
    __syncthreads();
    {   // pass 2: stats of LN1 output
        int p = tid>>1, half = tid&1;
        float m1=mu1[p], r1=rs1[p];
        float s=0.f, ss=0.f;
        const float* row = &T[p*97 + half*48];
        const float* gg = &G1[half*48];
        const float* bb = &B1[half*48];
        #pragma unroll 8
        for (int c=0;c<48;c++){ float t=(row[c]-m1)*r1*gg[c]+bb[c]; s+=t; ss+=t*t; }
        s  += __shfl_xor_sync(0xffffffffu, s, 1);
        ss += __shfl_xor_sync(0xffffffffu, ss, 1);
        if (half==0){
            float m = s*(1.f/96.f);
            mu2[p]=m; rs2[p]=rsqrtf(ss*(1.f/96.f)-m*m+1e-6f);
        }
    }
    __syncthreads();
    {   // pass 3: finalize + a*z + ysum
        int c = tid;
        float g1=G1[c], b1=B1[c], g2=G2[c], b2=B2[c];
        float ysum=0.f;
        for (int w=0; w<48; w++){
            float o = T[w*97+c];
            float t  = (o-mu1[w])*rs1[w]*g1 + b1;
            float z2 = (t-mu2[w])*rs2[w]*g2 + b2;
            int po = even ? (w*48+hr) : ((47-hr)*48+(47-w));
            float a = g_a[((size_t)qb*LL+po)*96 + c];
            float y = a*z2;
            ysum += y;
            g_y[((size_t)qb*LL+po)*96 + c] = y;
        }
        atomicAdd(&g_ysum[qb*96+c], ysum);
    }
}

// =============== K5: channel attention ===============
__global__ __launch_bounds__(96) void k5_att(const float* __restrict__ w1, const float* __restrict__ b1,
                                             const float* __restrict__ w2, const float* __restrict__ b2)
{
    __shared__ float sv[96], tv[12];
    int qb = blockIdx.x, q = qb>>4, c = threadIdx.x;
    sv[c] = g_ysum[qb*96+c] * (1.f/2304.f);
    __syncthreads();
    if (c<12){
        float acc = b1[q*12+c];
        #pragma unroll 8
        for (int cc=0; cc<96; cc++) acc += w1[(q*12+c)*96+cc]*sv[cc];
        tv[c] = siluf(acc);
    }
    __syncthreads();
    float acc = b2[q*96+c];
    #pragma unroll
    for (int r=0;r<12;r++) acc += w2[(q*96+c)*12+r]*tv[r];
    g_att[qb*96+c] = 1.f/(1.f+__expf(-acc));
}

// =============== K6: residual + att + transpose to NCHW ===============
__global__ __launch_bounds__(256) void k6_fin(const float* __restrict__ x, float* __restrict__ out)
{
    __shared__ float tile[96*49];
    __shared__ float atts[96];
    int qb = blockIdx.x, q = qb>>4, bb = qb&15, hr = blockIdx.y;
    int qh=(q>>1)*48, qw=(q&1)*48;
    const float* src = g_y + ((size_t)qb*LL + hr*48)*96;
    for (int i=threadIdx.x; i<48*96; i+=256){
        int w=i/96, c=i%96;
        tile[c*49+w] = src[i];
    }
    for (int i=threadIdx.x; i<96; i+=256) atts[i]=g_att[qb*96+i];
    __syncthreads();
    for (int i=threadIdx.x; i<96*48; i+=256){
        int c=i/48, w=i%48;
        size_t oi = ((size_t)(bb*96+c)*96 + qh+hr)*96 + qw + w;
        out[oi] = x[oi] + tile[c*49+w]*atts[c];
    }
}

// ================================================================
extern "C" void kernel_launch(void* const* d_in, const int* in_sizes, int n_in,
                              void* d_out, int out_size)
{
    const float* x    = (const float*)d_in[0];
    const float* ln_g = (const float*)d_in[1];
    const float* ln_b = (const float*)d_in[2];
    const float* p1w  = (const float*)d_in[3];
    const float* p1b  = (const float*)d_in[4];
    const float* p2w  = (const float*)d_in[5];
    const float* p2b  = (const float*)d_in[6];
    const float* dww  = (const float*)d_in[7];
    const float* dwb  = (const float*)d_in[8];
    const float* xprj = (const float*)d_in[9];
    const float* dtw  = (const float*)d_in[10];
    const float* dtb  = (const float*)d_in[11];
    const float* alog = (const float*)d_in[12];
    const float* dsv  = (const float*)d_in[13];
    const float* ssg  = (const float*)d_in[14];
    const float* ssb  = (const float*)d_in[15];
    const float* png  = (const float*)d_in[16];
    const float* pnb  = (const float*)d_in[17];
    const float* cw1  = (const float*)d_in[18];
    const float* cb1  = (const float*)d_in[19];
    const float* cw2  = (const float*)d_in[20];
    const float* cb2  = (const float*)d_in[21];
    const int*   bidx = (const int*)  d_in[22];
    float* out = (float*)d_out;

    const int smem_k1 = (96*K1XS + 96*K1WS)*4;   // 125184
    const int smem_k2 = 3*48*96*4;               // 55296
    const int smem_k3 = (96*K3XS + 96*K3WS)*4;   // 119040
    cudaFuncSetAttribute(k1_gemm, cudaFuncAttributeMaxDynamicSharedMemorySize, smem_k1);
    cudaFuncSetAttribute(k2_dw,   cudaFuncAttributeMaxDynamicSharedMemorySize, smem_k2);
    cudaFuncSetAttribute(k3_proj, cudaFuncAttributeMaxDynamicSharedMemorySize, smem_k3);

    k0_ln  <<<dim3(64,48), 256>>>(x, ln_g, ln_b);
    k1_gemm<<<dim3(288,4), 256, smem_k1>>>(p1w, p1b, p2w, p2b);
    k2_dw  <<<dim3(64,48), 256, smem_k2>>>(dww, dwb, bidx);
    k3_proj<<<dim3(144,2,4), 256, smem_k3>>>(xprj);
    k_scan <<<dim3(64,4), 96>>>(dtw, dtb, alog, dsv);
    k4_comb<<<dim3(64,48), 96>>>(ssg, ssb, png, pnb, bidx);
    k5_att <<<64, 96>>>(cw1, cb1, cw2, cb2);
    k6_fin <<<dim3(64,48), 256>>>(x, out);
}

// round 4
// speedup vs baseline: 1.1164x; 1.1164x over previous
#include <cuda_runtime.h>
#include <cuda_bf16.h>
#include <cstdint>

// problem constants
#define CC   96
#define LL   2304            // 48*48
#define NBQ  64              // 4 quads * 16 batch
#define PXQ  36864           // 16*2304 pixels per quadrant
#define NPL  24              // xdbl planes: dts 0-5, (6,7 pad), B 8-15, C 16-23

// ---------------- static scratch ----------------
__device__ float g_hln [NBQ*LL*CC];
__device__ float g_a   [NBQ*LL*CC];
__device__ float g_zin [NBQ*LL*CC];
__device__ float g_vf  [NBQ*LL*CC];
__device__ float g_vt  [NBQ*LL*CC];
__device__ float g_xdbl[NBQ*4*NPL*LL];   // plane-major
__device__ float g_ys  [NBQ*4*LL*CC];
__device__ float g_y   [NBQ*LL*CC];
__device__ float g_ysum[NBQ*CC];
__device__ float g_att [NBQ*CC];

__device__ __forceinline__ float siluf(float v){ return v * (1.f/(1.f+__expf(-v))); }

__device__ __forceinline__ void fma2(unsigned long long &acc, unsigned long long a, unsigned long long b){
    asm("fma.rn.f32x2 %0,%1,%2,%0;" : "+l"(acc) : "l"(a), "l"(b));
}
__device__ __forceinline__ unsigned long long pack2(float v){
    unsigned long long r; asm("mov.b64 %0,{%1,%1};" : "=l"(r) : "f"(v)); return r;
}
__device__ __forceinline__ float2 unpack2(unsigned long long v){
    float2 r; asm("mov.b64 {%0,%1},%2;" : "=f"(r.x), "=f"(r.y) : "l"(v)); return r;
}
__device__ __forceinline__ void cpasync16(void* dst, const void* src){
    unsigned d = (unsigned)__cvta_generic_to_shared(dst);
    asm volatile("cp.async.ca.shared.global [%0],[%1],16;" :: "r"(d), "l"(src));
}

// =============== K0: channel LN of x -> g_hln (pixel-major) ===============
__global__ __launch_bounds__(256) void k0_ln(const float* __restrict__ x,
                                             const float* __restrict__ lg,
                                             const float* __restrict__ lb)
{
    __shared__ float tile[96*49];
    __shared__ float mu_s[48], rs_s[48];
    int qb = blockIdx.x, q = qb>>4, bb = qb&15, hr = blockIdx.y;
    if (blockIdx.x==0 && blockIdx.y==0)
        for (int i=threadIdx.x; i<NBQ*CC; i+=256) g_ysum[i]=0.f;
    int qh=(q>>1)*48, qw=(q&1)*48;
    const float* xb = x + (size_t)bb*96*96*96 + (size_t)(qh+hr)*96 + qw;
    for (int i=threadIdx.x; i<96*48; i+=256){
        int c=i/48, w=i%48;
        tile[c*49+w] = xb[(size_t)c*9216 + w];
    }
    __syncthreads();
    if (threadIdx.x < 48){
        int w=threadIdx.x; float s=0.f, ss=0.f;
        #pragma unroll 8
        for (int c=0;c<96;c++){ float v=tile[c*49+w]; s+=v; ss+=v*v; }
        float m=s*(1.f/96.f); float var=ss*(1.f/96.f)-m*m;
        mu_s[w]=m; rs_s[w]=rsqrtf(var+1e-6f);
    }
    __syncthreads();
    const float* gg=lg+q*96; const float* bv=lb+q*96;
    float* out = g_hln + ((size_t)qb*LL + hr*48)*96;
    for (int i=threadIdx.x; i<48*96; i+=256){
        int w=i/96, c=i%96;
        out[i] = (tile[c*49+w]-mu_s[w])*rs_s[w]*gg[c] + bv[c];
    }
}

// =============== K1: 1x1 conv GEMM (conv split over grid.y), staged epilogue ===============
// grid (288, 2, 4), block 256 = 16 tp(px) x 16 tc(oc). Tile 128 px x 96 oc.
#define K1XS 132
#define K1WS 98
__global__ __launch_bounds__(256,2) void k1_gemm(const float* __restrict__ p1w, const float* __restrict__ p1b,
                                                 const float* __restrict__ p2w, const float* __restrict__ p2b)
{
    extern __shared__ float sm[];
    float* Xs = sm;                 // [96][132], reused as s_out[128][98]
    float* Ws = sm + 96*K1XS;       // [96][98]
    int q = blockIdx.z, conv = blockIdx.y, P0 = blockIdx.x*128;
    const float* base = g_hln + ((size_t)q*PXQ + P0)*96;
    for (int i=threadIdx.x; i<128*96; i+=256){ int p=i/96, c=i%96; Xs[c*K1XS+p] = base[i]; }
    const float* W = (conv? p2w : p1w) + (size_t)q*9216;
    for (int i=threadIdx.x; i<9216; i+=256){ int d=i/96, c=i%96; Ws[c*K1WS+d] = W[i]; }
    __syncthreads();
    int tp = threadIdx.x & 15, tc = threadIdx.x >> 4;
    unsigned long long acc[6][4];
    #pragma unroll
    for (int j=0;j<6;j++){ acc[j][0]=0ull; acc[j][1]=0ull; acc[j][2]=0ull; acc[j][3]=0ull; }
    const float* xb = Xs + 8*tp;
    const float* wb = Ws + 6*tc;
    #pragma unroll 2
    for (int k=0;k<96;k++){
        ulonglong2 x0 = *(const ulonglong2*)(xb + k*K1XS);
        ulonglong2 x1 = *(const ulonglong2*)(xb + k*K1XS + 4);
        const float* wr = wb + k*K1WS;
        float2 a0 = *(const float2*)(wr);
        float2 a1 = *(const float2*)(wr+2);
        float2 a2 = *(const float2*)(wr+4);
        float wf[6] = {a0.x,a0.y,a1.x,a1.y,a2.x,a2.y};
        #pragma unroll
        for (int j=0;j<6;j++){
            unsigned long long wv = pack2(wf[j]);
            fma2(acc[j][0], x0.x, wv);
            fma2(acc[j][1], x0.y, wv);
            fma2(acc[j][2], x1.x, wv);
            fma2(acc[j][3], x1.y, wv);
        }
    }
    const float* bias = (conv? p2b : p1b) + q*96;
    float bs[6];
    #pragma unroll
    for (int j=0;j<6;j++) bs[j]=bias[6*tc+j];
    __syncthreads();                 // all reads of Xs/Ws done
    float* sout = Xs;                // [128][98]
    #pragma unroll
    for (int i=0;i<4;i++){
        int p = 8*tp + 2*i;
        #pragma unroll
        for (int j=0;j<6;j++){
            float2 v = unpack2(acc[j][i]);
            sout[(size_t)p*98     + 6*tc+j] = v.x + bs[j];
            sout[(size_t)(p+1)*98 + 6*tc+j] = v.y + bs[j];
        }
    }
    __syncthreads();
    float* dst = (conv? g_zin : g_a) + ((size_t)q*PXQ + P0)*96;
    if (conv){
        for (int i=threadIdx.x; i<128*96; i+=256){
            int p=i/96, oc=i%96;
            dst[i] = sout[p*98+oc];
        }
    } else {
        for (int i=threadIdx.x; i<128*96; i+=256){
            int p=i/96, oc=i%96;
            dst[i] = siluf(sout[p*98+oc]);
        }
    }
}

// =============== K2: depthwise 3x3 + bias + silu + pre-transform ===============
__global__ __launch_bounds__(256) void k2_dw(const float* __restrict__ dww, const float* __restrict__ dwb,
                                             const int* __restrict__ bidx)
{
    extern __shared__ float rows[];         // [3][48*96]
    __shared__ float wsm[96*9];
    __shared__ float bsm[96];
    int qb = blockIdx.x, q = qb>>4, hr = blockIdx.y;
    for (int i=threadIdx.x; i<96*9; i+=256) wsm[i]=dww[q*96*9 + i];
    for (int i=threadIdx.x; i<96;   i+=256) bsm[i]=dwb[q*96 + i];
    for (int dy=0; dy<3; dy++){
        int hh = hr-1+dy;
        if (hh>=0 && hh<48){
            const float* src = g_zin + ((size_t)qb*LL + hh*48)*96;
            for (int i=threadIdx.x; i<48*96; i+=256) rows[dy*4608+i]=src[i];
        } else {
            for (int i=threadIdx.x; i<48*96; i+=256) rows[dy*4608+i]=0.f;
        }
    }
    __syncthreads();
    bool even = ((bidx[0] & 1) == 0);
    for (int i=threadIdx.x; i<48*96; i+=256){
        int w=i/96, c=i%96;
        float acc = bsm[c];
        #pragma unroll
        for (int dy=0; dy<3; dy++){
            #pragma unroll
            for (int dx=0; dx<3; dx++){
                int ww = w+dx-1;
                if (ww>=0 && ww<48) acc += wsm[c*9+dy*3+dx]*rows[dy*4608 + ww*96 + c];
            }
        }
        float z = siluf(acc);
        int pf, pt;
        if (even){ pf = w*48+hr;           pt = hr*48+w; }
        else     { pf = (47-hr)*48+(47-w); pt = (47-w)*48+(47-hr); }
        g_vf[((size_t)qb*LL + pf)*96 + c] = z;
        g_vt[((size_t)qb*LL + pt)*96 + c] = z;
    }
}

// =============== K3: x-projection GEMM -> plane layout ===============
// grid (288, 2, 4), block 256 = 16 tp(px) x 16 tc(oc, 3 each). Tile 128 px x 48 oc.
#define K3XS 132
#define K3WS 50
__global__ __launch_bounds__(256,3) void k3_proj(const float* __restrict__ xprojw)
{
    extern __shared__ float sm[];
    float* Xs = sm;                // [96][132]
    float* Ws = sm + 96*K3XS;      // [96][50]
    int q = blockIdx.z, src = blockIdx.y, P0 = blockIdx.x*128;
    const float* base = (src? g_vt : g_vf) + ((size_t)q*PXQ + P0)*96;
    for (int i=threadIdx.x; i<128*96; i+=256){ int p=i/96, c=i%96; Xs[c*K3XS+p]=base[i]; }
    for (int i=threadIdx.x; i<48*96; i+=256){
        int oc=i/96, kk=i%96;
        float v=0.f;
        if (oc<44){
            int k = (oc<22)? src : src+2;
            int d = (oc<22)? oc : oc-22;
            v = xprojw[(((size_t)q*4 + k)*22 + d)*96 + kk];
        }
        Ws[kk*K3WS+oc]=v;
    }
    __syncthreads();
    int tp = threadIdx.x & 15, tc = threadIdx.x >> 4;
    unsigned long long acc[3][4];
    #pragma unroll
    for (int j=0;j<3;j++){ acc[j][0]=0ull; acc[j][1]=0ull; acc[j][2]=0ull; acc[j][3]=0ull; }
    const float* xb = Xs + 8*tp;
    const float* wb = Ws + 3*tc;
    #pragma unroll 2
    for (int k=0;k<96;k++){
        ulonglong2 x0 = *(const ulonglong2*)(xb + k*K3XS);
        ulonglong2 x1 = *(const ulonglong2*)(xb + k*K3XS + 4);
        const float* wr = wb + k*K3WS;
        #pragma unroll
        for (int j=0;j<3;j++){
            unsigned long long wv = pack2(wr[j]);
            fma2(acc[j][0], x0.x, wv);
            fma2(acc[j][1], x0.y, wv);
            fma2(acc[j][2], x1.x, wv);
            fma2(acc[j][3], x1.y, wv);
        }
    }
    int b = P0 / LL;
    int l0 = P0 % LL + 8*tp;
    int qb = q*16 + b;
    #pragma unroll
    for (int j=0;j<3;j++){
        int oc = 3*tc+j;
        if (oc>=44) continue;
        int kdir = (oc<22)? src : src+2;
        int d    = (oc<22)? oc : oc-22;
        int plane= (d<6)? d : d+2;
        float* dst = g_xdbl + (((size_t)qb*4 + kdir)*NPL + plane)*LL + l0;
        float2 v0 = unpack2(acc[j][0]);
        float2 v1 = unpack2(acc[j][1]);
        float2 v2 = unpack2(acc[j][2]);
        float2 v3 = unpack2(acc[j][3]);
        *(float4*)(dst)   = make_float4(v0.x,v0.y,v1.x,v1.y);
        *(float4*)(dst+4) = make_float4(v2.x,v2.y,v3.x,v3.y);
    }
}

// =============== K-scan: selective scan, 1 thread per (q,b,k,c) lane ===============
__global__ __launch_bounds__(96) void k_scan(const float* __restrict__ dtw_g, const float* __restrict__ dtb_g,
                                             const float* __restrict__ alog_g, const float* __restrict__ ds_g)
{
    __shared__ float s_u [2][16*96];
    __shared__ float s_xd[2][NPL*16];
    int qb = blockIdx.x, k = blockIdx.y, q = qb>>4;
    int c = threadIdx.x;
    int pidx = (q*4+k)*96 + c;
    float dtw[6];
    #pragma unroll
    for (int r=0;r<6;r++) dtw[r]=dtw_g[pidx*6+r];
    float dtb = dtb_g[pidx];
    float Ac[8];
    #pragma unroll
    for (int n=0;n<8;n++) Ac[n] = -__expf(alog_g[pidx*8+n]);
    float Dv = ds_g[pidx];
    const float* u_base  = ((k&1)? g_vt : g_vf) + (size_t)qb*LL*96;
    const float* xd_base = g_xdbl + ((size_t)qb*4+k)*NPL*LL;
    float* ys_base = g_ys + ((size_t)qb*4+k)*LL*96;
    bool rev = (k>=2);
    int plane = c>>2, piece = c&3;
    float hs[8];
    #pragma unroll
    for (int n=0;n<8;n++) hs[n]=0.f;
    {
        int sst = rev ? (LL-16) : 0;
        const float4* us = (const float4*)(u_base + (size_t)sst*96);
        #pragma unroll
        for (int j=0;j<4;j++) cpasync16(&s_u[0][(j*96+c)*4], &us[j*96+c]);
        cpasync16(&s_xd[0][plane*16 + piece*4], xd_base + (size_t)plane*LL + sst + piece*4);
        asm volatile("cp.async.commit_group;");
    }
    for (int cs=0; cs<144; cs++){
        if (cs<143){
            int cn = cs+1;
            int sst = rev ? (LL - 16*(cn+1)) : 16*cn;
            int buf = cn & 1;
            const float4* us = (const float4*)(u_base + (size_t)sst*96);
            #pragma unroll
            for (int j=0;j<4;j++) cpasync16(&s_u[buf][(j*96+c)*4], &us[j*96+c]);
            cpasync16(&s_xd[buf][plane*16 + piece*4], xd_base + (size_t)plane*LL + sst + piece*4);
            asm volatile("cp.async.commit_group;");
            asm volatile("cp.async.wait_group 1;");
        } else {
            asm volatile("cp.async.wait_group 0;");
        }
        __syncthreads();
        int buf = cs & 1;
        int sst = rev ? (LL - 16*(cs+1)) : 16*cs;
        const float* xd = &s_xd[buf][0];
        #pragma unroll 4
        for (int j=0;j<16;j++){
            int off = rev ? (15-j) : j;
            float draw = dtb + dtw[0]*xd[0*16+off] + dtw[1]*xd[1*16+off] + dtw[2]*xd[2*16+off]
                             + dtw[3]*xd[3*16+off] + dtw[4]*xd[4*16+off] + dtw[5]*xd[5*16+off];
            float delta = (draw > 15.f) ? draw : __logf(1.f + __expf(draw));
            float u = s_u[buf][off*96 + c];
            float du = delta*u;
            float y = Dv*u;
            hs[0] = __expf(delta*Ac[0])*hs[0] + du*xd[( 8)*16+off];  y += hs[0]*xd[(16)*16+off];
            hs[1] = __expf(delta*Ac[1])*hs[1] + du*xd[( 9)*16+off];  y += hs[1]*xd[(17)*16+off];
            hs[2] = __expf(delta*Ac[2])*hs[2] + du*xd[(10)*16+off];  y += hs[2]*xd[(18)*16+off];
            hs[3] = __expf(delta*Ac[3])*hs[3] + du*xd[(11)*16+off];  y += hs[3]*xd[(19)*16+off];
            hs[4] = __expf(delta*Ac[4])*hs[4] + du*xd[(12)*16+off];  y += hs[4]*xd[(20)*16+off];
            hs[5] = __expf(delta*Ac[5])*hs[5] + du*xd[(13)*16+off];  y += hs[5]*xd[(21)*16+off];
            hs[6] = __expf(delta*Ac[6])*hs[6] + du*xd[(14)*16+off];  y += hs[6]*xd[(22)*16+off];
            hs[7] = __expf(delta*Ac[7])*hs[7] + du*xd[(15)*16+off];  y += hs[7]*xd[(23)*16+off];
            ys_base[(size_t)(sst+off)*96 + c] = y;
        }
        __syncthreads();
    }
}

// =============== K4: combine 4 dirs + ssln LN + p2n LN + a*z + ysum ===============
__global__ __launch_bounds__(96) void k4_comb(const float* __restrict__ g1g, const float* __restrict__ b1g,
                                              const float* __restrict__ g2g, const float* __restrict__ b2g,
                                              const int* __restrict__ bidx)
{
    __shared__ float T[48*97];
    __shared__ float mu1[48], rs1[48], mu2[48], rs2[48];
    __shared__ float G1[96], B1[96], G2[96], B2[96];
    int qb = blockIdx.x, q = qb>>4, hr = blockIdx.y, tid = threadIdx.x;
    bool even = ((bidx[0] & 1) == 0);
    G1[tid]=g1g[q*96+tid]; B1[tid]=b1g[q*96+tid];
    G2[tid]=g2g[q*96+tid]; B2[tid]=b2g[q*96+tid];
    size_t ysq = (size_t)qb*4;
    const float* y0 = g_ys + (ysq+0)*LL*96;
    const float* y1 = g_ys + (ysq+1)*LL*96;
    const float* y2 = g_ys + (ysq+2)*LL*96;
    const float* y3 = g_ys + (ysq+3)*LL*96;
    for (int i=tid; i<48*96; i+=96){
        int w=i/96, c=i%96;
        int lf=hr*48+w, lt=w*48+hr;
        T[w*97+c] = y0[(size_t)lf*96+c] + y2[(size_t)lf*96+c]
                  + y1[(size_t)lt*96+c] + y3[(size_t)lt*96+c];
    }
    __syncthreads();
    {
        int p = tid>>1, half = tid&1;
        float s=0.f, ss=0.f;
        const float* row = &T[p*97 + half*48];
        #pragma unroll 8
        for (int c=0;c<48;c++){ float v=row[c]; s+=v; ss+=v*v; }
        s  += __shfl_xor_sync(0xffffffffu, s, 1);
        ss += __shfl_xor_sync(0xffffffffu, ss, 1);
        if (half==0){
            float m = s*(1.f/96.f);
            mu1[p]=m; rs1[p]=rsqrtf(ss*(1.f/96.f)-m*m+1e-6f);
        }
    }
    __syncthreads();
    {
        int p = tid>>1, half = tid&1;
        float m1=mu1[p], r1=rs1[p];
        float s=0.f, ss=0.f;
        const float* row = &T[p*97 + half*48];
        const float* gg = &G1[half*48];
        const float* bb = &B1[half*48];
        #pragma unroll 8
        for (int c=0;c<48;c++){ float t=(row[c]-m1)*r1*gg[c]+bb[c]; s+=t; ss+=t*t; }
        s  += __shfl_xor_sync(0xffffffffu, s, 1);
        ss += __shfl_xor_sync(0xffffffffu, ss, 1);
        if (half==0){
            float m = s*(1.f/96.f);
            mu2[p]=m; rs2[p]=rsqrtf(ss*(1.f/96.f)-m*m+1e-6f);
        }
    }
    __syncthreads();
    {
        int c = tid;
        float g1=G1[c], b1=B1[c], g2=G2[c], b2=B2[c];
        float ysum=0.f;
        for (int w=0; w<48; w++){
            float o = T[w*97+c];
            float t  = (o-mu1[w])*rs1[w]*g1 + b1;
            float z2 = (t-mu2[w])*rs2[w]*g2 + b2;
            int po = even ? (w*48+hr) : ((47-hr)*48+(47-w));
            float a = g_a[((size_t)qb*LL+po)*96 + c];
            float y = a*z2;
            ysum += y;
            g_y[((size_t)qb*LL+po)*96 + c] = y;
        }
        atomicAdd(&g_ysum[qb*96+c], ysum);
    }
}

// =============== K5: channel attention ===============
__global__ __launch_bounds__(96) void k5_att(const float* __restrict__ w1, const float* __restrict__ b1,
                                             const float* __restrict__ w2, const float* __restrict__ b2)
{
    __shared__ float sv[96], tv[12];
    int qb = blockIdx.x, q = qb>>4, c = threadIdx.x;
    sv[c] = g_ysum[qb*96+c] * (1.f/2304.f);
    __syncthreads();
    if (c<12){
        float acc = b1[q*12+c];
        #pragma unroll 8
        for (int cc=0; cc<96; cc++) acc += w1[(q*12+c)*96+cc]*sv[cc];
        tv[c] = siluf(acc);
    }
    __syncthreads();
    float acc = b2[q*96+c];
    #pragma unroll
    for (int r=0;r<12;r++) acc += w2[(q*96+c)*12+r]*tv[r];
    g_att[qb*96+c] = 1.f/(1.f+__expf(-acc));
}

// =============== K6: residual + att + transpose to NCHW ===============
__global__ __launch_bounds__(256) void k6_fin(const float* __restrict__ x, float* __restrict__ out)
{
    __shared__ float tile[96*49];
    __shared__ float atts[96];
    int qb = blockIdx.x, q = qb>>4, bb = qb&15, hr = blockIdx.y;
    int qh=(q>>1)*48, qw=(q&1)*48;
    const float* src = g_y + ((size_t)qb*LL + hr*48)*96;
    for (int i=threadIdx.x; i<48*96; i+=256){
        int w=i/96, c=i%96;
        tile[c*49+w] = src[i];
    }
    for (int i=threadIdx.x; i<96; i+=256) atts[i]=g_att[qb*96+i];
    __syncthreads();
    for (int i=threadIdx.x; i<96*48; i+=256){
        int c=i/48, w=i%48;
        size_t oi = ((size_t)(bb*96+c)*96 + qh+hr)*96 + qw + w;
        out[oi] = x[oi] + tile[c*49+w]*atts[c];
    }
}

// ================================================================
extern "C" void kernel_launch(void* const* d_in, const int* in_sizes, int n_in,
                              void* d_out, int out_size)
{
    const float* x    = (const float*)d_in[0];
    const float* ln_g = (const float*)d_in[1];
    const float* ln_b = (const float*)d_in[2];
    const float* p1w  = (const float*)d_in[3];
    const float* p1b  = (const float*)d_in[4];
    const float* p2w  = (const float*)d_in[5];
    const float* p2b  = (const float*)d_in[6];
    const float* dww  = (const float*)d_in[7];
    const float* dwb  = (const float*)d_in[8];
    const float* xprj = (const float*)d_in[9];
    const float* dtw  = (const float*)d_in[10];
    const float* dtb  = (const float*)d_in[11];
    const float* alog = (const float*)d_in[12];
    const float* dsv  = (const float*)d_in[13];
    const float* ssg  = (const float*)d_in[14];
    const float* ssb  = (const float*)d_in[15];
    const float* png  = (const float*)d_in[16];
    const float* pnb  = (const float*)d_in[17];
    const float* cw1  = (const float*)d_in[18];
    const float* cb1  = (const float*)d_in[19];
    const float* cw2  = (const float*)d_in[20];
    const float* cb2  = (const float*)d_in[21];
    const int*   bidx = (const int*)  d_in[22];
    float* out = (float*)d_out;

    const int smem_k1 = (96*K1XS + 96*K1WS)*4;   // 88320
    const int smem_k2 = 3*48*96*4;               // 55296
    const int smem_k3 = (96*K3XS + 96*K3WS)*4;   // 69888
    cudaFuncSetAttribute(k1_gemm, cudaFuncAttributeMaxDynamicSharedMemorySize, smem_k1);
    cudaFuncSetAttribute(k2_dw,   cudaFuncAttributeMaxDynamicSharedMemorySize, smem_k2);
    cudaFuncSetAttribute(k3_proj, cudaFuncAttributeMaxDynamicSharedMemorySize, smem_k3);

    k0_ln  <<<dim3(64,48), 256>>>(x, ln_g, ln_b);
    k1_gemm<<<dim3(288,2,4), 256, smem_k1>>>(p1w, p1b, p2w, p2b);
    k2_dw  <<<dim3(64,48), 256, smem_k2>>>(dww, dwb, bidx);
    k3_proj<<<dim3(288,2,4), 256, smem_k3>>>(xprj);
    k_scan <<<dim3(64,4), 96>>>(dtw, dtb, alog, dsv);
    k4_comb<<<dim3(64,48), 96>>>(ssg, ssb, png, pnb, bidx);
    k5_att <<<64, 96>>>(cw1, cb1, cw2, cb2);
    k6_fin <<<dim3(64,48), 256>>>(x, out);
}

// round 5
// speedup vs baseline: 1.1248x; 1.0075x over previous
#include <cuda_runtime.h>
#include <cuda_bf16.h>
#include <cstdint>

// problem constants
#define CC   96
#define LL   2304            // 48*48
#define NBQ  64              // 4 quads * 16 batch
#define PXQ  36864           // 16*2304 pixels per quadrant
#define NPL  24              // xdbl planes: dts 0-5, (6,7 pad), B 8-15, C 16-23

// ---------------- static scratch ----------------
__device__ float g_hln [NBQ*LL*CC];
__device__ float g_a   [NBQ*LL*CC];
__device__ float g_zin [NBQ*LL*CC];
__device__ float g_vf  [NBQ*LL*CC];
__device__ float g_vt  [NBQ*LL*CC];
__device__ float g_xdbl[NBQ*4*NPL*LL];   // plane-major
__device__ float g_ys  [NBQ*4*LL*CC];
__device__ float g_y   [NBQ*LL*CC];
__device__ float g_ysum[NBQ*CC];
__device__ float g_att [NBQ*CC];

__device__ __forceinline__ float siluf(float v){ return v * (1.f/(1.f+__expf(-v))); }

__device__ __forceinline__ void fma2(unsigned long long &acc, unsigned long long a, unsigned long long b){
    asm("fma.rn.f32x2 %0,%1,%2,%0;" : "+l"(acc) : "l"(a), "l"(b));
}
__device__ __forceinline__ unsigned long long pack2(float v){
    unsigned long long r; asm("mov.b64 %0,{%1,%1};" : "=l"(r) : "f"(v)); return r;
}
__device__ __forceinline__ float2 unpack2(unsigned long long v){
    float2 r; asm("mov.b64 {%0,%1},%2;" : "=f"(r.x), "=f"(r.y) : "l"(v)); return r;
}
__device__ __forceinline__ void cpasync16(void* dst, const void* src){
    unsigned d = (unsigned)__cvta_generic_to_shared(dst);
    asm volatile("cp.async.ca.shared.global [%0],[%1],16;" :: "r"(d), "l"(src));
}

// =============== K0: channel LN of x -> g_hln (pixel-major) ===============
__global__ __launch_bounds__(256) void k0_ln(const float* __restrict__ x,
                                             const float* __restrict__ lg,
                                             const float* __restrict__ lb)
{
    __shared__ float tile[96*49];
    __shared__ float mu_s[48], rs_s[48];
    int qb = blockIdx.x, q = qb>>4, bb = qb&15, hr = blockIdx.y;
    if (blockIdx.x==0 && blockIdx.y==0)
        for (int i=threadIdx.x; i<NBQ*CC; i+=256) g_ysum[i]=0.f;
    int qh=(q>>1)*48, qw=(q&1)*48;
    const float* xb = x + (size_t)bb*96*96*96 + (size_t)(qh+hr)*96 + qw;
    for (int i=threadIdx.x; i<96*48; i+=256){
        int c=i/48, w=i%48;
        tile[c*49+w] = xb[(size_t)c*9216 + w];
    }
    __syncthreads();
    if (threadIdx.x < 48){
        int w=threadIdx.x; float s=0.f, ss=0.f;
        #pragma unroll 8
        for (int c=0;c<96;c++){ float v=tile[c*49+w]; s+=v; ss+=v*v; }
        float m=s*(1.f/96.f); float var=ss*(1.f/96.f)-m*m;
        mu_s[w]=m; rs_s[w]=rsqrtf(var+1e-6f);
    }
    __syncthreads();
    const float* gg=lg+q*96; const float* bv=lb+q*96;
    float* out = g_hln + ((size_t)qb*LL + hr*48)*96;
    for (int i=threadIdx.x; i<48*96; i+=256){
        int w=i/96, c=i%96;
        out[i] = (tile[c*49+w]-mu_s[w])*rs_s[w]*gg[c] + bv[c];
    }
}

// =============== K1: BOTH 1x1 convs fused, 64px x 192oc tile ===============
// grid (576, 4), block 256 = 16 tp(4px) x 16 tc(12oc: 6 conv0 + 6 conv1).
#define F1XS 68
#define F1WS 196
__global__ __launch_bounds__(256,2) void k1_gemm(const float* __restrict__ p1w, const float* __restrict__ p1b,
                                                 const float* __restrict__ p2w, const float* __restrict__ p2b)
{
    extern __shared__ float sm[];
    float* Xs = sm;                 // [96][68]
    float* Ws = sm + 96*F1XS;       // [96][196] : conv0 d 0..95, conv1 d 96..191
    int q = blockIdx.y, P0 = blockIdx.x*64;
    const float* base = g_hln + ((size_t)q*PXQ + P0)*96;
    for (int i=threadIdx.x; i<64*96; i+=256){ int p=i/96, c=i%96; Xs[c*F1XS+p] = base[i]; }
    const float* W0 = p1w + (size_t)q*9216;
    const float* W1 = p2w + (size_t)q*9216;
    for (int i=threadIdx.x; i<9216; i+=256){
        int d=i/96, c=i%96;
        Ws[c*F1WS+d]    = W0[i];
        Ws[c*F1WS+96+d] = W1[i];
    }
    __syncthreads();
    int tp = threadIdx.x & 15, tc = threadIdx.x >> 4;
    unsigned long long acc[12][2];
    #pragma unroll
    for (int j=0;j<12;j++){ acc[j][0]=0ull; acc[j][1]=0ull; }
    const float* xb = Xs + 4*tp;
    const float* wb = Ws + 6*tc;
    #pragma unroll 4
    for (int k=0;k<96;k++){
        ulonglong2 xv = *(const ulonglong2*)(xb + k*F1XS);
        const float* wr = wb + k*F1WS;
        float2 a0 = *(const float2*)(wr);
        float2 a1 = *(const float2*)(wr+2);
        float2 a2 = *(const float2*)(wr+4);
        float2 b0 = *(const float2*)(wr+96);
        float2 b1 = *(const float2*)(wr+98);
        float2 b2 = *(const float2*)(wr+100);
        float wf[12] = {a0.x,a0.y,a1.x,a1.y,a2.x,a2.y, b0.x,b0.y,b1.x,b1.y,b2.x,b2.y};
        #pragma unroll
        for (int j=0;j<12;j++){
            unsigned long long wv = pack2(wf[j]);
            fma2(acc[j][0], xv.x, wv);
            fma2(acc[j][1], xv.y, wv);
        }
    }
    float bs0[6], bs1[6];
    #pragma unroll
    for (int j=0;j<6;j++){ bs0[j]=p1b[q*96+6*tc+j]; bs1[j]=p2b[q*96+6*tc+j]; }
    __syncthreads();                  // done reading Xs/Ws
    float* sout = sm;                 // [64][100]
    // ---- conv0 -> silu -> g_a ----
    #pragma unroll
    for (int i=0;i<2;i++){
        int p = 4*tp + 2*i;
        #pragma unroll
        for (int j=0;j<6;j++){
            float2 v = unpack2(acc[j][i]);
            sout[(size_t)p*100     + 6*tc+j] = v.x + bs0[j];
            sout[(size_t)(p+1)*100 + 6*tc+j] = v.y + bs0[j];
        }
    }
    __syncthreads();
    {
        float* dst = g_a + ((size_t)q*PXQ + P0)*96;
        for (int i=threadIdx.x; i<64*96; i+=256){
            int p=i/96, oc=i%96;
            dst[i] = siluf(sout[p*100+oc]);
        }
    }
    __syncthreads();
    // ---- conv1 -> g_zin ----
    #pragma unroll
    for (int i=0;i<2;i++){
        int p = 4*tp + 2*i;
        #pragma unroll
        for (int j=0;j<6;j++){
            float2 v = unpack2(acc[6+j][i]);
            sout[(size_t)p*100     + 6*tc+j] = v.x + bs1[j];
            sout[(size_t)(p+1)*100 + 6*tc+j] = v.y + bs1[j];
        }
    }
    __syncthreads();
    {
        float* dst = g_zin + ((size_t)q*PXQ + P0)*96;
        for (int i=threadIdx.x; i<64*96; i+=256){
            int p=i/96, oc=i%96;
            dst[i] = sout[p*100+oc];
        }
    }
}

// =============== K2: depthwise 3x3 + bias + silu + pre-transform ===============
__global__ __launch_bounds__(256) void k2_dw(const float* __restrict__ dww, const float* __restrict__ dwb,
                                             const int* __restrict__ bidx)
{
    extern __shared__ float rows[];         // [3][48*96]
    __shared__ float wsm[96*9];
    __shared__ float bsm[96];
    int qb = blockIdx.x, q = qb>>4, hr = blockIdx.y;
    for (int i=threadIdx.x; i<96*9; i+=256) wsm[i]=dww[q*96*9 + i];
    for (int i=threadIdx.x; i<96;   i+=256) bsm[i]=dwb[q*96 + i];
    for (int dy=0; dy<3; dy++){
        int hh = hr-1+dy;
        if (hh>=0 && hh<48){
            const float* src = g_zin + ((size_t)qb*LL + hh*48)*96;
            for (int i=threadIdx.x; i<48*96; i+=256) rows[dy*4608+i]=src[i];
        } else {
            for (int i=threadIdx.x; i<48*96; i+=256) rows[dy*4608+i]=0.f;
        }
    }
    __syncthreads();
    bool even = ((bidx[0] & 1) == 0);
    for (int i=threadIdx.x; i<48*96; i+=256){
        int w=i/96, c=i%96;
        float acc = bsm[c];
        #pragma unroll
        for (int dy=0; dy<3; dy++){
            #pragma unroll
            for (int dx=0; dx<3; dx++){
                int ww = w+dx-1;
                if (ww>=0 && ww<48) acc += wsm[c*9+dy*3+dx]*rows[dy*4608 + ww*96 + c];
            }
        }
        float z = siluf(acc);
        int pf, pt;
        if (even){ pf = w*48+hr;           pt = hr*48+w; }
        else     { pf = (47-hr)*48+(47-w); pt = (47-w)*48+(47-hr); }
        g_vf[((size_t)qb*LL + pf)*96 + c] = z;
        g_vt[((size_t)qb*LL + pt)*96 + c] = z;
    }
}

// =============== K3: x-projection GEMM -> plane layout ===============
// grid (288, 2, 4), block 256 = 16 tp(px) x 16 tc(oc, 3 each). Tile 128 px x 48 oc.
#define K3XS 132
#define K3WS 50
__global__ __launch_bounds__(256,3) void k3_proj(const float* __restrict__ xprojw)
{
    extern __shared__ float sm[];
    float* Xs = sm;                // [96][132]
    float* Ws = sm + 96*K3XS;      // [96][50]
    int q = blockIdx.z, src = blockIdx.y, P0 = blockIdx.x*128;
    const float* base = (src? g_vt : g_vf) + ((size_t)q*PXQ + P0)*96;
    for (int i=threadIdx.x; i<128*96; i+=256){ int p=i/96, c=i%96; Xs[c*K3XS+p]=base[i]; }
    for (int i=threadIdx.x; i<48*96; i+=256){
        int oc=i/96, kk=i%96;
        float v=0.f;
        if (oc<44){
            int k = (oc<22)? src : src+2;
            int d = (oc<22)? oc : oc-22;
            v = xprojw[(((size_t)q*4 + k)*22 + d)*96 + kk];
        }
        Ws[kk*K3WS+oc]=v;
    }
    __syncthreads();
    int tp = threadIdx.x & 15, tc = threadIdx.x >> 4;
    unsigned long long acc[3][4];
    #pragma unroll
    for (int j=0;j<3;j++){ acc[j][0]=0ull; acc[j][1]=0ull; acc[j][2]=0ull; acc[j][3]=0ull; }
    const float* xb = Xs + 8*tp;
    const float* wb = Ws + 3*tc;
    #pragma unroll 4
    for (int k=0;k<96;k++){
        ulonglong2 x0 = *(const ulonglong2*)(xb + k*K3XS);
        ulonglong2 x1 = *(const ulonglong2*)(xb + k*K3XS + 4);
        const float* wr = wb + k*K3WS;
        #pragma unroll
        for (int j=0;j<3;j++){
            unsigned long long wv = pack2(wr[j]);
            fma2(acc[j][0], x0.x, wv);
            fma2(acc[j][1], x0.y, wv);
            fma2(acc[j][2], x1.x, wv);
            fma2(acc[j][3], x1.y, wv);
        }
    }
    int b = P0 / LL;
    int l0 = P0 % LL + 8*tp;
    int qb = q*16 + b;
    #pragma unroll
    for (int j=0;j<3;j++){
        int oc = 3*tc+j;
        if (oc>=44) continue;
        int kdir = (oc<22)? src : src+2;
        int d    = (oc<22)? oc : oc-22;
        int plane= (d<6)? d : d+2;
        float* dst = g_xdbl + (((size_t)qb*4 + kdir)*NPL + plane)*LL + l0;
        float2 v0 = unpack2(acc[j][0]);
        float2 v1 = unpack2(acc[j][1]);
        float2 v2 = unpack2(acc[j][2]);
        float2 v3 = unpack2(acc[j][3]);
        *(float4*)(dst)   = make_float4(v0.x,v0.y,v1.x,v1.y);
        *(float4*)(dst+4) = make_float4(v2.x,v2.y,v3.x,v3.y);
    }
}

// =============== K-scan: selective scan, 1 thread per (q,b,k,c) lane ===============
__global__ __launch_bounds__(96) void k_scan(const float* __restrict__ dtw_g, const float* __restrict__ dtb_g,
                                             const float* __restrict__ alog_g, const float* __restrict__ ds_g)
{
    __shared__ float s_u [2][16*96];
    __shared__ float s_xd[2][NPL*16];
    int qb = blockIdx.x, k = blockIdx.y, q = qb>>4;
    int c = threadIdx.x;
    int pidx = (q*4+k)*96 + c;
    float dtw[6];
    #pragma unroll
    for (int r=0;r<6;r++) dtw[r]=dtw_g[pidx*6+r];
    float dtb = dtb_g[pidx];
    float Ac[8];
    #pragma unroll
    for (int n=0;n<8;n++) Ac[n] = -__expf(alog_g[pidx*8+n]);
    float Dv = ds_g[pidx];
    const float* u_base  = ((k&1)? g_vt : g_vf) + (size_t)qb*LL*96;
    const float* xd_base = g_xdbl + ((size_t)qb*4+k)*NPL*LL;
    float* ys_base = g_ys + ((size_t)qb*4+k)*LL*96;
    bool rev = (k>=2);
    int plane = c>>2, piece = c&3;
    float hs[8];
    #pragma unroll
    for (int n=0;n<8;n++) hs[n]=0.f;
    {
        int sst = rev ? (LL-16) : 0;
        const float4* us = (const float4*)(u_base + (size_t)sst*96);
        #pragma unroll
        for (int j=0;j<4;j++) cpasync16(&s_u[0][(j*96+c)*4], &us[j*96+c]);
        cpasync16(&s_xd[0][plane*16 + piece*4], xd_base + (size_t)plane*LL + sst + piece*4);
        asm volatile("cp.async.commit_group;");
    }
    for (int cs=0; cs<144; cs++){
        if (cs<143){
            int cn = cs+1;
            int sst = rev ? (LL - 16*(cn+1)) : 16*cn;
            int buf = cn & 1;
            const float4* us = (const float4*)(u_base + (size_t)sst*96);
            #pragma unroll
            for (int j=0;j<4;j++) cpasync16(&s_u[buf][(j*96+c)*4], &us[j*96+c]);
            cpasync16(&s_xd[buf][plane*16 + piece*4], xd_base + (size_t)plane*LL + sst + piece*4);
            asm volatile("cp.async.commit_group;");
            asm volatile("cp.async.wait_group 1;");
        } else {
            asm volatile("cp.async.wait_group 0;");
        }
        __syncthreads();
        int buf = cs & 1;
        int sst = rev ? (LL - 16*(cs+1)) : 16*cs;
        const float* xd = &s_xd[buf][0];
        #pragma unroll 4
        for (int j=0;j<16;j++){
            int off = rev ? (15-j) : j;
            float draw = dtb + dtw[0]*xd[0*16+off] + dtw[1]*xd[1*16+off] + dtw[2]*xd[2*16+off]
                             + dtw[3]*xd[3*16+off] + dtw[4]*xd[4*16+off] + dtw[5]*xd[5*16+off];
            float delta = (draw > 15.f) ? draw : __logf(1.f + __expf(draw));
            float u = s_u[buf][off*96 + c];
            float du = delta*u;
            float y = Dv*u;
            hs[0] = __expf(delta*Ac[0])*hs[0] + du*xd[( 8)*16+off];  y += hs[0]*xd[(16)*16+off];
            hs[1] = __expf(delta*Ac[1])*hs[1] + du*xd[( 9)*16+off];  y += hs[1]*xd[(17)*16+off];
            hs[2] = __expf(delta*Ac[2])*hs[2] + du*xd[(10)*16+off];  y += hs[2]*xd[(18)*16+off];
            hs[3] = __expf(delta*Ac[3])*hs[3] + du*xd[(11)*16+off];  y += hs[3]*xd[(19)*16+off];
            hs[4] = __expf(delta*Ac[4])*hs[4] + du*xd[(12)*16+off];  y += hs[4]*xd[(20)*16+off];
            hs[5] = __expf(delta*Ac[5])*hs[5] + du*xd[(13)*16+off];  y += hs[5]*xd[(21)*16+off];
            hs[6] = __expf(delta*Ac[6])*hs[6] + du*xd[(14)*16+off];  y += hs[6]*xd[(22)*16+off];
            hs[7] = __expf(delta*Ac[7])*hs[7] + du*xd[(15)*16+off];  y += hs[7]*xd[(23)*16+off];
            ys_base[(size_t)(sst+off)*96 + c] = y;
        }
        __syncthreads();
    }
}

// =============== K4: combine 4 dirs + ssln LN + p2n LN + a*z + ysum ===============
__global__ __launch_bounds__(96) void k4_comb(const float* __restrict__ g1g, const float* __restrict__ b1g,
                                              const float* __restrict__ g2g, const float* __restrict__ b2g,
                                              const int* __restrict__ bidx)
{
    __shared__ float T[48*97];
    __shared__ float mu1[48], rs1[48], mu2[48], rs2[48];
    __shared__ float G1[96], B1[96], G2[96], B2[96];
    int qb = blockIdx.x, q = qb>>4, hr = blockIdx.y, tid = threadIdx.x;
    bool even = ((bidx[0] & 1) == 0);
    G1[tid]=g1g[q*96+tid]; B1[tid]=b1g[q*96+tid];
    G2[tid]=g2g[q*96+tid]; B2[tid]=b2g[q*96+tid];
    size_t ysq = (size_t)qb*4;
    const float* y0 = g_ys + (ysq+0)*LL*96;
    const float* y1 = g_ys + (ysq+1)*LL*96;
    const float* y2 = g_ys + (ysq+2)*LL*96;
    const float* y3 = g_ys + (ysq+3)*LL*96;
    for (int i=tid; i<48*96; i+=96){
        int w=i/96, c=i%96;
        int lf=hr*48+w, lt=w*48+hr;
        T[w*97+c] = y0[(size_t)lf*96+c] + y2[(size_t)lf*96+c]
                  + y1[(size_t)lt*96+c] + y3[(size_t)lt*96+c];
    }
    __syncthreads();
    {
        int p = tid>>1, half = tid&1;
        float s=0.f, ss=0.f;
        const float* row = &T[p*97 + half*48];
        #pragma unroll 8
        for (int c=0;c<48;c++){ float v=row[c]; s+=v; ss+=v*v; }
        s  += __shfl_xor_sync(0xffffffffu, s, 1);
        ss += __shfl_xor_sync(0xffffffffu, ss, 1);
        if (half==0){
            float m = s*(1.f/96.f);
            mu1[p]=m; rs1[p]=rsqrtf(ss*(1.f/96.f)-m*m+1e-6f);
        }
    }
    __syncthreads();
    {
        int p = tid>>1, half = tid&1;
        float m1=mu1[p], r1=rs1[p];
        float s=0.f, ss=0.f;
        const float* row = &T[p*97 + half*48];
        const float* gg = &G1[half*48];
        const float* bb = &B1[half*48];
        #pragma unroll 8
        for (int c=0;c<48;c++){ float t=(row[c]-m1)*r1*gg[c]+bb[c]; s+=t; ss+=t*t; }
        s  += __shfl_xor_sync(0xffffffffu, s, 1);
        ss += __shfl_xor_sync(0xffffffffu, ss, 1);
        if (half==0){
            float m = s*(1.f/96.f);
            mu2[p]=m; rs2[p]=rsqrtf(ss*(1.f/96.f)-m*m+1e-6f);
        }
    }
    __syncthreads();
    {
        int c = tid;
        float g1=G1[c], b1=B1[c], g2=G2[c], b2=B2[c];
        float ysum=0.f;
        for (int w=0; w<48; w++){
            float o = T[w*97+c];
            float t  = (o-mu1[w])*rs1[w]*g1 + b1;
            float z2 = (t-mu2[w])*rs2[w]*g2 + b2;
            int po = even ? (w*48+hr) : ((47-hr)*48+(47-w));
            float a = g_a[((size_t)qb*LL+po)*96 + c];
            float y = a*z2;
            ysum += y;
            g_y[((size_t)qb*LL+po)*96 + c] = y;
        }
        atomicAdd(&g_ysum[qb*96+c], ysum);
    }
}

// =============== K5: channel attention ===============
__global__ __launch_bounds__(96) void k5_att(const float* __restrict__ w1, const float* __restrict__ b1,
                                             const float* __restrict__ w2, const float* __restrict__ b2)
{
    __shared__ float sv[96], tv[12];
    int qb = blockIdx.x, q = qb>>4, c = threadIdx.x;
    sv[c] = g_ysum[qb*96+c] * (1.f/2304.f);
    __syncthreads();
    if (c<12){
        float acc = b1[q*12+c];
        #pragma unroll 8
        for (int cc=0; cc<96; cc++) acc += w1[(q*12+c)*96+cc]*sv[cc];
        tv[c] = siluf(acc);
    }
    __syncthreads();
    float acc = b2[q*96+c];
    #pragma unroll
    for (int r=0;r<12;r++) acc += w2[(q*96+c)*12+r]*tv[r];
    g_att[qb*96+c] = 1.f/(1.f+__expf(-acc));
}

// =============== K6: residual + att + transpose to NCHW ===============
__global__ __launch_bounds__(256) void k6_fin(const float* __restrict__ x, float* __restrict__ out)
{
    __shared__ float tile[96*49];
    __shared__ float atts[96];
    int qb = blockIdx.x, q = qb>>4, bb = qb&15, hr = blockIdx.y;
    int qh=(q>>1)*48, qw=(q&1)*48;
    const float* src = g_y + ((size_t)qb*LL + hr*48)*96;
    for (int i=threadIdx.x; i<48*96; i+=256){
        int w=i/96, c=i%96;
        tile[c*49+w] = src[i];
    }
    for (int i=threadIdx.x; i<96; i+=256) atts[i]=g_att[qb*96+i];
    __syncthreads();
    for (int i=threadIdx.x; i<96*48; i+=256){
        int c=i/48, w=i%48;
        size_t oi = ((size_t)(bb*96+c)*96 + qh+hr)*96 + qw + w;
        out[oi] = x[oi] + tile[c*49+w]*atts[c];
    }
}

// ================================================================
extern "C" void kernel_launch(void* const* d_in, const int* in_sizes, int n_in,
                              void* d_out, int out_size)
{
    const float* x    = (const float*)d_in[0];
    const float* ln_g = (const float*)d_in[1];
    const float* ln_b = (const float*)d_in[2];
    const float* p1w  = (const float*)d_in[3];
    const float* p1b  = (const float*)d_in[4];
    const float* p2w  = (const float*)d_in[5];
    const float* p2b  = (const float*)d_in[6];
    const float* dww  = (const float*)d_in[7];
    const float* dwb  = (const float*)d_in[8];
    const float* xprj = (const float*)d_in[9];
    const float* dtw  = (const float*)d_in[10];
    const float* dtb  = (const float*)d_in[11];
    const float* alog = (const float*)d_in[12];
    const float* dsv  = (const float*)d_in[13];
    const float* ssg  = (const float*)d_in[14];
    const float* ssb  = (const float*)d_in[15];
    const float* png  = (const float*)d_in[16];
    const float* pnb  = (const float*)d_in[17];
    const float* cw1  = (const float*)d_in[18];
    const float* cb1  = (const float*)d_in[19];
    const float* cw2  = (const float*)d_in[20];
    const float* cb2  = (const float*)d_in[21];
    const int*   bidx = (const int*)  d_in[22];
    float* out = (float*)d_out;

    const int smem_k1 = (96*F1XS + 96*F1WS)*4;   // 101376
    const int smem_k2 = 3*48*96*4;               // 55296
    const int smem_k3 = (96*K3XS + 96*K3WS)*4;   // 69888
    cudaFuncSetAttribute(k1_gemm, cudaFuncAttributeMaxDynamicSharedMemorySize, smem_k1);
    cudaFuncSetAttribute(k2_dw,   cudaFuncAttributeMaxDynamicSharedMemorySize, smem_k2);
    cudaFuncSetAttribute(k3_proj, cudaFuncAttributeMaxDynamicSharedMemorySize, smem_k3);

    k0_ln  <<<dim3(64,48), 256>>>(x, ln_g, ln_b);
    k1_gemm<<<dim3(576,4), 256, smem_k1>>>(p1w, p1b, p2w, p2b);
    k2_dw  <<<dim3(64,48), 256, smem_k2>>>(dww, dwb, bidx);
    k3_proj<<<dim3(288,2,4), 256, smem_k3>>>(xprj);
    k_scan <<<dim3(64,4), 96>>>(dtw, dtb, alog, dsv);
    k4_comb<<<dim3(64,48), 96>>>(ssg, ssb, png, pnb, bidx);
    k5_att <<<64, 96>>>(cw1, cb1, cw2, cb2);
    k6_fin <<<dim3(64,48), 256>>>(x, out);
}

// round 7
// speedup vs baseline: 1.1850x; 1.0535x over previous
#include <cuda_runtime.h>
#include <cuda_bf16.h>
#include <cstdint>

// problem constants
#define CC   96
#define LL   2304            // 48*48
#define NBQ  64              // 4 quads * 16 batch
#define PXQ  36864           // 16*2304 pixels per quadrant
#define NPL  24              // xdbl planes: dts 0-5, (6,7 pad), B 8-15, C 16-23

// ---------------- static scratch ----------------
__device__ float g_hln [NBQ*LL*CC];
__device__ float g_a   [NBQ*LL*CC];
__device__ float g_zin [NBQ*LL*CC];
__device__ float g_vf  [NBQ*LL*CC];
__device__ float g_xdbl[NBQ*4*NPL*LL];   // plane-major
__device__ float g_y   [NBQ*LL*CC];      // combined scan output (z-space), atomic target
__device__ float g_yo  [NBQ*LL*CC];      // k4 output (orig pixel space)
__device__ float g_ysum[NBQ*CC];
__device__ float g_att [NBQ*CC];

__device__ __forceinline__ float siluf(float v){ return v * (1.f/(1.f+__expf(-v))); }

__device__ __forceinline__ void fma2(unsigned long long &acc, unsigned long long a, unsigned long long b){
    asm("fma.rn.f32x2 %0,%1,%2,%0;" : "+l"(acc) : "l"(a), "l"(b));
}
__device__ __forceinline__ unsigned long long pack2(float v){
    unsigned long long r; asm("mov.b64 %0,{%1,%1};" : "=l"(r) : "f"(v)); return r;
}
__device__ __forceinline__ float2 unpack2(unsigned long long v){
    float2 r; asm("mov.b64 {%0,%1},%2;" : "=f"(r.x), "=f"(r.y) : "l"(v)); return r;
}
__device__ __forceinline__ void cpasync16(void* dst, const void* src){
    unsigned d = (unsigned)__cvta_generic_to_shared(dst);
    asm volatile("cp.async.ca.shared.global [%0],[%1],16;" :: "r"(d), "l"(src));
}

// =============== K0: channel LN of x -> g_hln (pixel-major); zero g_y ===============
__global__ __launch_bounds__(256) void k0_ln(const float* __restrict__ x,
                                             const float* __restrict__ lg,
                                             const float* __restrict__ lb)
{
    __shared__ float tile[96*49];
    __shared__ float mu_s[48], rs_s[48];
    int qb = blockIdx.x, q = qb>>4, bb = qb&15, hr = blockIdx.y;
    if (blockIdx.x==0 && blockIdx.y==0)
        for (int i=threadIdx.x; i<NBQ*CC; i+=256) g_ysum[i]=0.f;
    {
        float* yz = g_y + ((size_t)qb*LL + hr*48)*96;
        for (int i=threadIdx.x; i<48*96; i+=256) yz[i]=0.f;
    }
    int qh=(q>>1)*48, qw=(q&1)*48;
    const float* xb = x + (size_t)bb*96*96*96 + (size_t)(qh+hr)*96 + qw;
    for (int i=threadIdx.x; i<96*48; i+=256){
        int c=i/48, w=i%48;
        tile[c*49+w] = xb[(size_t)c*9216 + w];
    }
    __syncthreads();
    if (threadIdx.x < 48){
        int w=threadIdx.x; float s=0.f, ss=0.f;
        #pragma unroll 8
        for (int c=0;c<96;c++){ float v=tile[c*49+w]; s+=v; ss+=v*v; }
        float m=s*(1.f/96.f); float var=ss*(1.f/96.f)-m*m;
        mu_s[w]=m; rs_s[w]=rsqrtf(var+1e-6f);
    }
    __syncthreads();
    const float* gg=lg+q*96; const float* bv=lb+q*96;
    float* out = g_hln + ((size_t)qb*LL + hr*48)*96;
    for (int i=threadIdx.x; i<48*96; i+=256){
        int w=i/96, c=i%96;
        out[i] = (tile[c*49+w]-mu_s[w])*rs_s[w]*gg[c] + bv[c];
    }
}

// =============== K1: BOTH 1x1 convs fused, 64px x 192oc tile ===============
#define F1XS 68
#define F1WS 196
__global__ __launch_bounds__(256,2) void k1_gemm(const float* __restrict__ p1w, const float* __restrict__ p1b,
                                                 const float* __restrict__ p2w, const float* __restrict__ p2b)
{
    extern __shared__ float sm[];
    float* Xs = sm;                 // [96][68]
    float* Ws = sm + 96*F1XS;       // [96][196]
    int q = blockIdx.y, P0 = blockIdx.x*64;
    const float* base = g_hln + ((size_t)q*PXQ + P0)*96;
    for (int i=threadIdx.x; i<64*96; i+=256){ int p=i/96, c=i%96; Xs[c*F1XS+p] = base[i]; }
    const float* W0 = p1w + (size_t)q*9216;
    const float* W1 = p2w + (size_t)q*9216;
    for (int i=threadIdx.x; i<9216; i+=256){
        int d=i/96, c=i%96;
        Ws[c*F1WS+d]    = W0[i];
        Ws[c*F1WS+96+d] = W1[i];
    }
    __syncthreads();
    int tp = threadIdx.x & 15, tc = threadIdx.x >> 4;
    unsigned long long acc[12][2];
    #pragma unroll
    for (int j=0;j<12;j++){ acc[j][0]=0ull; acc[j][1]=0ull; }
    const float* xb = Xs + 4*tp;
    const float* wb = Ws + 6*tc;
    #pragma unroll 4
    for (int k=0;k<96;k++){
        ulonglong2 xv = *(const ulonglong2*)(xb + k*F1XS);
        const float* wr = wb + k*F1WS;
        float2 a0 = *(const float2*)(wr);
        float2 a1 = *(const float2*)(wr+2);
        float2 a2 = *(const float2*)(wr+4);
        float2 b0 = *(const float2*)(wr+96);
        float2 b1 = *(const float2*)(wr+98);
        float2 b2 = *(const float2*)(wr+100);
        float wf[12] = {a0.x,a0.y,a1.x,a1.y,a2.x,a2.y, b0.x,b0.y,b1.x,b1.y,b2.x,b2.y};
        #pragma unroll
        for (int j=0;j<12;j++){
            unsigned long long wv = pack2(wf[j]);
            fma2(acc[j][0], xv.x, wv);
            fma2(acc[j][1], xv.y, wv);
        }
    }
    float bs0[6], bs1[6];
    #pragma unroll
    for (int j=0;j<6;j++){ bs0[j]=p1b[q*96+6*tc+j]; bs1[j]=p2b[q*96+6*tc+j]; }
    __syncthreads();
    float* sout = sm;                 // [64][100]
    #pragma unroll
    for (int i=0;i<2;i++){
        int p = 4*tp + 2*i;
        #pragma unroll
        for (int j=0;j<6;j++){
            float2 v = unpack2(acc[j][i]);
            sout[(size_t)p*100     + 6*tc+j] = v.x + bs0[j];
            sout[(size_t)(p+1)*100 + 6*tc+j] = v.y + bs0[j];
        }
    }
    __syncthreads();
    {
        float* dst = g_a + ((size_t)q*PXQ + P0)*96;
        for (int i=threadIdx.x; i<64*96; i+=256){
            int p=i/96, oc=i%96;
            dst[i] = siluf(sout[p*100+oc]);
        }
    }
    __syncthreads();
    #pragma unroll
    for (int i=0;i<2;i++){
        int p = 4*tp + 2*i;
        #pragma unroll
        for (int j=0;j<6;j++){
            float2 v = unpack2(acc[6+j][i]);
            sout[(size_t)p*100     + 6*tc+j] = v.x + bs1[j];
            sout[(size_t)(p+1)*100 + 6*tc+j] = v.y + bs1[j];
        }
    }
    __syncthreads();
    {
        float* dst = g_zin + ((size_t)q*PXQ + P0)*96;
        for (int i=threadIdx.x; i<64*96; i+=256){
            int p=i/96, oc=i%96;
            dst[i] = sout[p*100+oc];
        }
    }
}

// =============== K2: depthwise 3x3 + bias + silu + pre-transform -> g_vf only ===============
__global__ __launch_bounds__(256) void k2_dw(const float* __restrict__ dww, const float* __restrict__ dwb,
                                             const int* __restrict__ bidx)
{
    extern __shared__ float rows[];         // [3][48*96]
    __shared__ float wsm[96*9];
    __shared__ float bsm[96];
    int qb = blockIdx.x, q = qb>>4, hr = blockIdx.y;
    for (int i=threadIdx.x; i<96*9; i+=256) wsm[i]=dww[q*96*9 + i];
    for (int i=threadIdx.x; i<96;   i+=256) bsm[i]=dwb[q*96 + i];
    for (int dy=0; dy<3; dy++){
        int hh = hr-1+dy;
        if (hh>=0 && hh<48){
            const float* src = g_zin + ((size_t)qb*LL + hh*48)*96;
            for (int i=threadIdx.x; i<48*96; i+=256) rows[dy*4608+i]=src[i];
        } else {
            for (int i=threadIdx.x; i<48*96; i+=256) rows[dy*4608+i]=0.f;
        }
    }
    __syncthreads();
    bool even = ((bidx[0] & 1) == 0);
    for (int i=threadIdx.x; i<48*96; i+=256){
        int w=i/96, c=i%96;
        float acc = bsm[c];
        #pragma unroll
        for (int dy=0; dy<3; dy++){
            #pragma unroll
            for (int dx=0; dx<3; dx++){
                int ww = w+dx-1;
                if (ww>=0 && ww<48) acc += wsm[c*9+dy*3+dx]*rows[dy*4608 + ww*96 + c];
            }
        }
        float z = siluf(acc);
        int pf = even ? (w*48+hr) : ((47-hr)*48+(47-w));
        g_vf[((size_t)qb*LL + pf)*96 + c] = z;
    }
}

// =============== K3: x-projection GEMM -> plane layout (src=1 reads vf transposed) ===============
#define K3XS 132
#define K3WS 50
__global__ __launch_bounds__(256,3) void k3_proj(const float* __restrict__ xprojw)
{
    extern __shared__ float sm[];
    float* Xs = sm;                // [96][132]
    float* Ws = sm + 96*K3XS;      // [96][50]
    int q = blockIdx.z, src = blockIdx.y, P0 = blockIdx.x*128;
    int b_img = P0 / LL;
    int l0 = P0 % LL;
    const float* vbase = g_vf + (size_t)(q*16 + b_img)*LL*96;
    for (int i=threadIdx.x; i<128*96; i+=256){
        int p=i/96, c=i%96;
        int l = l0 + p;
        int row = src ? ((l%48)*48 + l/48) : l;
        Xs[c*K3XS+p] = vbase[(size_t)row*96 + c];
    }
    for (int i=threadIdx.x; i<48*96; i+=256){
        int oc=i/96, kk=i%96;
        float v=0.f;
        if (oc<44){
            int k = (oc<22)? src : src+2;
            int d = (oc<22)? oc : oc-22;
            v = xprojw[(((size_t)q*4 + k)*22 + d)*96 + kk];
        }
        Ws[kk*K3WS+oc]=v;
    }
    __syncthreads();
    int tp = threadIdx.x & 15, tc = threadIdx.x >> 4;
    unsigned long long acc[3][4];
    #pragma unroll
    for (int j=0;j<3;j++){ acc[j][0]=0ull; acc[j][1]=0ull; acc[j][2]=0ull; acc[j][3]=0ull; }
    const float* xb = Xs + 8*tp;
    const float* wb = Ws + 3*tc;
    #pragma unroll 4
    for (int k=0;k<96;k++){
        ulonglong2 x0 = *(const ulonglong2*)(xb + k*K3XS);
        ulonglong2 x1 = *(const ulonglong2*)(xb + k*K3XS + 4);
        const float* wr = wb + k*K3WS;
        #pragma unroll
        for (int j=0;j<3;j++){
            unsigned long long wv = pack2(wr[j]);
            fma2(acc[j][0], x0.x, wv);
            fma2(acc[j][1], x0.y, wv);
            fma2(acc[j][2], x1.x, wv);
            fma2(acc[j][3], x1.y, wv);
        }
    }
    int qb = q*16 + b_img;
    int lw = l0 + 8*tp;
    #pragma unroll
    for (int j=0;j<3;j++){
        int oc = 3*tc+j;
        if (oc>=44) continue;
        int kdir = (oc<22)? src : src+2;
        int d    = (oc<22)? oc : oc-22;
        int plane= (d<6)? d : d+2;
        float* dst = g_xdbl + (((size_t)qb*4 + kdir)*NPL + plane)*LL + lw;
        float2 v0 = unpack2(acc[j][0]);
        float2 v1 = unpack2(acc[j][1]);
        float2 v2 = unpack2(acc[j][2]);
        float2 v3 = unpack2(acc[j][3]);
        *(float4*)(dst)   = make_float4(v0.x,v0.y,v1.x,v1.y);
        *(float4*)(dst+4) = make_float4(v2.x,v2.y,v3.x,v3.y);
    }
}

// =============== K-scan: selective scan, atomic-combine into g_y ===============
__global__ __launch_bounds__(96) void k_scan(const float* __restrict__ dtw_g, const float* __restrict__ dtb_g,
                                             const float* __restrict__ alog_g, const float* __restrict__ ds_g)
{
    __shared__ float s_u [2][16*96];
    __shared__ float s_xd[2][NPL*16];
    int qb = blockIdx.x, k = blockIdx.y, q = qb>>4;
    int c = threadIdx.x;
    int pidx = (q*4+k)*96 + c;
    float dtw[6];
    #pragma unroll
    for (int r=0;r<6;r++) dtw[r]=dtw_g[pidx*6+r];
    float dtb = dtb_g[pidx];
    float Ac[8];
    #pragma unroll
    for (int n=0;n<8;n++) Ac[n] = -__expf(alog_g[pidx*8+n]);
    float Dv = ds_g[pidx];
    const float* u_base  = g_vf + (size_t)qb*LL*96;
    const float* xd_base = g_xdbl + ((size_t)qb*4+k)*NPL*LL;
    float* y_base = g_y + (size_t)qb*LL*96;
    bool rev = (k>=2);
    int kt = k & 1;
    int plane = c>>2, piece = c&3;
    float hs[8];
    #pragma unroll
    for (int n=0;n<8;n++) hs[n]=0.f;

    auto load_u = [&](int buf, int sst){
        int a0 = sst/48, b0 = sst%48;
        #pragma unroll
        for (int jj=0;jj<4;jj++){
            int pc = c + 96*jj;
            int off = pc/24, fo = pc%24;
            int row = kt ? ((b0+off)*48 + a0) : (sst+off);
            cpasync16(&s_u[buf][off*96 + fo*4], u_base + (size_t)row*96 + fo*4);
        }
        cpasync16(&s_xd[buf][plane*16 + piece*4], xd_base + (size_t)plane*LL + sst + piece*4);
    };

    {
        int sst = rev ? (LL-16) : 0;
        load_u(0, sst);
        asm volatile("cp.async.commit_group;");
    }
    for (int cs=0; cs<144; cs++){
        if (cs<143){
            int cn = cs+1;
            int sst = rev ? (LL - 16*(cn+1)) : 16*cn;
            load_u(cn & 1, sst);
            asm volatile("cp.async.commit_group;");
            asm volatile("cp.async.wait_group 1;");
        } else {
            asm volatile("cp.async.wait_group 0;");
        }
        __syncthreads();
        int buf = cs & 1;
        int sst = rev ? (LL - 16*(cs+1)) : 16*cs;
        int a0 = sst/48, b0 = sst%48;
        const float* xd = &s_xd[buf][0];
        #pragma unroll 4
        for (int j=0;j<16;j++){
            int off = rev ? (15-j) : j;
            float draw = dtb + dtw[0]*xd[0*16+off] + dtw[1]*xd[1*16+off] + dtw[2]*xd[2*16+off]
                             + dtw[3]*xd[3*16+off] + dtw[4]*xd[4*16+off] + dtw[5]*xd[5*16+off];
            float delta = (draw > 15.f) ? draw : __logf(1.f + __expf(draw));
            float u = s_u[buf][off*96 + c];
            float du = delta*u;
            float y = Dv*u;
            hs[0] = __expf(delta*Ac[0])*hs[0] + du*xd[( 8)*16+off];  y += hs[0]*xd[(16)*16+off];
            hs[1] = __expf(delta*Ac[1])*hs[1] + du*xd[( 9)*16+off];  y += hs[1]*xd[(17)*16+off];
            hs[2] = __expf(delta*Ac[2])*hs[2] + du*xd[(10)*16+off];  y += hs[2]*xd[(18)*16+off];
            hs[3] = __expf(delta*Ac[3])*hs[3] + du*xd[(11)*16+off];  y += hs[3]*xd[(19)*16+off];
            hs[4] = __expf(delta*Ac[4])*hs[4] + du*xd[(12)*16+off];  y += hs[4]*xd[(20)*16+off];
            hs[5] = __expf(delta*Ac[5])*hs[5] + du*xd[(13)*16+off];  y += hs[5]*xd[(21)*16+off];
            hs[6] = __expf(delta*Ac[6])*hs[6] + du*xd[(14)*16+off];  y += hs[6]*xd[(22)*16+off];
            hs[7] = __expf(delta*Ac[7])*hs[7] + du*xd[(15)*16+off];  y += hs[7]*xd[(23)*16+off];
            int row = kt ? ((b0+off)*48 + a0) : (sst+off);
            atomicAdd(&y_base[(size_t)row*96 + c], y);
        }
        __syncthreads();
    }
}

// =============== K4: ssln LN + p2n LN + a*z + ysum (reads combined g_y) ===============
__global__ __launch_bounds__(96) void k4_comb(const float* __restrict__ g1g, const float* __restrict__ b1g,
                                              const float* __restrict__ g2g, const float* __restrict__ b2g,
                                              const int* __restrict__ bidx)
{
    __shared__ float T[48*97];
    __shared__ float mu1[48], rs1[48], mu2[48], rs2[48];
    __shared__ float G1[96], B1[96], G2[96], B2[96];
    int qb = blockIdx.x, q = qb>>4, hr = blockIdx.y, tid = threadIdx.x;
    bool even = ((bidx[0] & 1) == 0);
    G1[tid]=g1g[q*96+tid]; B1[tid]=b1g[q*96+tid];
    G2[tid]=g2g[q*96+tid]; B2[tid]=b2g[q*96+tid];
    const float* yb = g_y + (size_t)qb*LL*96;
    // T[w][c] = combined ss2d output (z-space) that maps to orig pixel (hr, w)
    for (int i=tid; i<48*96; i+=96){
        int w=i/96, c=i%96;
        int pf = even ? (w*48+hr) : ((47-hr)*48+(47-w));
        T[w*97+c] = yb[(size_t)pf*96+c];
    }
    __syncthreads();
    {
        int p = tid>>1, half = tid&1;
        float s=0.f, ss=0.f;
        const float* row = &T[p*97 + half*48];
        #pragma unroll 8
        for (int c=0;c<48;c++){ float v=row[c]; s+=v; ss+=v*v; }
        s  += __shfl_xor_sync(0xffffffffu, s, 1);
        ss += __shfl_xor_sync(0xffffffffu, ss, 1);
        if (half==0){
            float m = s*(1.f/96.f);
            mu1[p]=m; rs1[p]=rsqrtf(ss*(1.f/96.f)-m*m+1e-6f);
        }
    }
    __syncthreads();
    {
        int p = tid>>1, half = tid&1;
        float m1=mu1[p], r1=rs1[p];
        float s=0.f, ss=0.f;
        const float* row = &T[p*97 + half*48];
        const float* gg = &G1[half*48];
        const float* bb = &B1[half*48];
        #pragma unroll 8
        for (int c=0;c<48;c++){ float t=(row[c]-m1)*r1*gg[c]+bb[c]; s+=t; ss+=t*t; }
        s  += __shfl_xor_sync(0xffffffffu, s, 1);
        ss += __shfl_xor_sync(0xffffffffu, ss, 1);
        if (half==0){
            float m = s*(1.f/96.f);
            mu2[p]=m; rs2[p]=rsqrtf(ss*(1.f/96.f)-m*m+1e-6f);
        }
    }
    __syncthreads();
    {
        int c = tid;
        float g1=G1[c], b1=B1[c], g2=G2[c], b2=B2[c];
        float ysum=0.f;
        const float* ab = g_a  + ((size_t)qb*LL + hr*48)*96;
        float*       yo = g_yo + ((size_t)qb*LL + hr*48)*96;
        for (int w=0; w<48; w++){
            float o = T[w*97+c];
            float t  = (o-mu1[w])*rs1[w]*g1 + b1;
            float z2 = (t-mu2[w])*rs2[w]*g2 + b2;
            float a = ab[(size_t)w*96 + c];     // orig pixel (hr, w)
            float y = a*z2;
            ysum += y;
            yo[(size_t)w*96 + c] = y;
        }
        atomicAdd(&g_ysum[qb*96+c], ysum);
    }
}

// =============== K5: channel attention ===============
__global__ __launch_bounds__(96) void k5_att(const float* __restrict__ w1, const float* __restrict__ b1,
                                             const float* __restrict__ w2, const float* __restrict__ b2)
{
    __shared__ float sv[96], tv[12];
    int qb = blockIdx.x, q = qb>>4, c = threadIdx.x;
    sv[c] = g_ysum[qb*96+c] * (1.f/2304.f);
    __syncthreads();
    if (c<12){
        float acc = b1[q*12+c];
        #pragma unroll 8
        for (int cc=0; cc<96; cc++) acc += w1[(q*12+c)*96+cc]*sv[cc];
        tv[c] = siluf(acc);
    }
    __syncthreads();
    float acc = b2[q*96+c];
    #pragma unroll
    for (int r=0;r<12;r++) acc += w2[(q*96+c)*12+r]*tv[r];
    g_att[qb*96+c] = 1.f/(1.f+__expf(-acc));
}

// =============== K6: residual + att + transpose to NCHW ===============
__global__ __launch_bounds__(256) void k6_fin(const float* __restrict__ x, float* __restrict__ out)
{
    __shared__ float tile[96*49];
    __shared__ float atts[96];
    int qb = blockIdx.x, q = qb>>4, bb = qb&15, hr = blockIdx.y;
    int qh=(q>>1)*48, qw=(q&1)*48;
    const float* src = g_yo + ((size_t)qb*LL + hr*48)*96;
    for (int i=threadIdx.x; i<48*96; i+=256){
        int w=i/96, c=i%96;
        tile[c*49+w] = src[i];
    }
    for (int i=threadIdx.x; i<96; i+=256) atts[i]=g_att[qb*96+i];
    __syncthreads();
    for (int i=threadIdx.x; i<96*48; i+=256){
        int c=i/48, w=i%48;
        size_t oi = ((size_t)(bb*96+c)*96 + qh+hr)*96 + qw + w;
        out[oi] = x[oi] + tile[c*49+w]*atts[c];
    }
}

// ================================================================
extern "C" void kernel_launch(void* const* d_in, const int* in_sizes, int n_in,
                              void* d_out, int out_size)
{
    const float* x    = (const float*)d_in[0];
    const float* ln_g = (const float*)d_in[1];
    const float* ln_b = (const float*)d_in[2];
    const float* p1w  = (const float*)d_in[3];
    const float* p1b  = (const float*)d_in[4];
    const float* p2w  = (const float*)d_in[5];
    const float* p2b  = (const float*)d_in[6];
    const float* dww  = (const float*)d_in[7];
    const float* dwb  = (const float*)d_in[8];
    const float* xprj = (const float*)d_in[9];
    const float* dtw  = (const float*)d_in[10];
    const float* dtb  = (const float*)d_in[11];
    const float* alog = (const float*)d_in[12];
    const float* dsv  = (const float*)d_in[13];
    const float* ssg  = (const float*)d_in[14];
    const float* ssb  = (const float*)d_in[15];
    const float* png  = (const float*)d_in[16];
    const float* pnb  = (const float*)d_in[17];
    const float* cw1  = (const float*)d_in[18];
    const float* cb1  = (const float*)d_in[19];
    const float* cw2  = (const float*)d_in[20];
    const float* cb2  = (const float*)d_in[21];
    const int*   bidx = (const int*)  d_in[22];
    float* out = (float*)d_out;

    const int smem_k1 = (96*F1XS + 96*F1WS)*4;   // 101376
    const int smem_k2 = 3*48*96*4;               // 55296
    const int smem_k3 = (96*K3XS + 96*K3WS)*4;   // 69888
    cudaFuncSetAttribute(k1_gemm, cudaFuncAttributeMaxDynamicSharedMemorySize, smem_k1);
    cudaFuncSetAttribute(k2_dw,   cudaFuncAttributeMaxDynamicSharedMemorySize, smem_k2);
    cudaFuncSetAttribute(k3_proj, cudaFuncAttributeMaxDynamicSharedMemorySize, smem_k3);

    k0_ln  <<<dim3(64,48), 256>>>(x, ln_g, ln_b);
    k1_gemm<<<dim3(576,4), 256, smem_k1>>>(p1w, p1b, p2w, p2b);
    k2_dw  <<<dim3(64,48), 256, smem_k2>>>(dww, dwb, bidx);
    k3_proj<<<dim3(288,2,4), 256, smem_k3>>>(xprj);
    k_scan <<<dim3(64,4), 96>>>(dtw, dtb, alog, dsv);
    k4_comb<<<dim3(64,48), 96>>>(ssg, ssb, png, pnb, bidx);
    k5_att <<<64, 96>>>(cw1, cb1, cw2, cb2);
    k6_fin <<<dim3(64,48), 256>>>(x, out);
}

// round 8
// speedup vs baseline: 1.2717x; 1.0732x over previous
#include <cuda_runtime.h>
#include <cuda_bf16.h>
#include <cstdint>

// problem constants
#define CC   96
#define LL   2304            // 48*48
#define NBQ  64              // 4 quads * 16 batch
#define PXQ  36864           // 16*2304 pixels per quadrant
#define NPL  24              // xdbl planes: dts 0-5, (6,7 pad), B 8-15, C 16-23

// ---------------- static scratch ----------------
__device__ float g_a   [NBQ*LL*CC];
__device__ float g_zin [NBQ*LL*CC];
__device__ float g_vf  [NBQ*LL*CC];
__device__ float g_xdbl[NBQ*4*NPL*LL];   // plane-major
__device__ float g_y   [NBQ*LL*CC];      // combined scan output (z-space), atomic target
__device__ float g_yo  [NBQ*LL*CC];      // k4 output (orig pixel space)
__device__ float g_ysum[NBQ*CC];
__device__ float g_att [NBQ*CC];

__device__ __forceinline__ float siluf(float v){ return v * (1.f/(1.f+__expf(-v))); }

__device__ __forceinline__ void fma2(unsigned long long &acc, unsigned long long a, unsigned long long b){
    asm("fma.rn.f32x2 %0,%1,%2,%0;" : "+l"(acc) : "l"(a), "l"(b));
}
__device__ __forceinline__ unsigned long long pack2(float v){
    unsigned long long r; asm("mov.b64 %0,{%1,%1};" : "=l"(r) : "f"(v)); return r;
}
__device__ __forceinline__ float2 unpack2(unsigned long long v){
    float2 r; asm("mov.b64 {%0,%1},%2;" : "=f"(r.x), "=f"(r.y) : "l"(v)); return r;
}
__device__ __forceinline__ void cpasync16(void* dst, const void* src){
    unsigned d = (unsigned)__cvta_generic_to_shared(dst);
    asm volatile("cp.async.ca.shared.global [%0],[%1],16;" :: "r"(d), "l"(src));
}

// =============== K1: LN + BOTH 1x1 convs fused, 64px x 192oc ===============
// grid (576, 4), block 256 = 16 tp(4px) x 16 tc(12oc via 6 pairs).
// tc 0-7 -> conv0 oc 0..95 ; tc 8-15 -> conv1 oc 0..95
#define X1S 68
#define W1S 198
__global__ __launch_bounds__(256,2) void k1_gemm(const float* __restrict__ x,
                                                 const float* __restrict__ lg, const float* __restrict__ lb,
                                                 const float* __restrict__ p1w, const float* __restrict__ p1b,
                                                 const float* __restrict__ p2w, const float* __restrict__ p2b)
{
    extern __shared__ float sm[];
    float* Xs = sm;                 // [96][68]
    float* Ws = sm + 96*X1S;        // [96][198]: cols 0..95 conv0 oc, 96..191 conv1 oc
    __shared__ float mu[64], rs[64];
    __shared__ float b0s[96], b1s[96];
    int q = blockIdx.y, P0 = blockIdx.x*64;
    int bb = P0 / LL, l0 = P0 % LL;
    int qh=(q>>1)*48, qw=(q&1)*48;
    const float* xb = x + (size_t)bb*884736 + (size_t)qh*96 + qw;
    // load x tile (NCHW gather, coalesced in w)
    for (int i=threadIdx.x; i<96*64; i+=256){
        int c=i>>6, p=i&63;
        int l=l0+p, h=l/48, w=l%48;
        Xs[c*X1S+p] = xb[(size_t)c*9216 + h*96 + w];
    }
    // load weights: Ws[k][oc] (no dup; pairs read via LDS.64)
    const float* W0 = p1w + (size_t)q*9216;
    const float* W1 = p2w + (size_t)q*9216;
    for (int i=threadIdx.x; i<9216; i+=256){
        int d=i/96, c=i%96;
        Ws[c*W1S+d]    = W0[i];
        Ws[c*W1S+96+d] = W1[i];
    }
    for (int i=threadIdx.x; i<96; i+=256){ b0s[i]=p1b[q*96+i]; b1s[i]=p2b[q*96+i]; }
    __syncthreads();
    // per-pixel LN stats: 4 threads per px
    {
        int px = threadIdx.x>>2, part = threadIdx.x&3;
        float s=0.f, ss=0.f;
        const float* col = Xs + px;
        #pragma unroll 8
        for (int cc=part*24; cc<part*24+24; cc++){ float v=col[cc*X1S]; s+=v; ss+=v*v; }
        s  += __shfl_xor_sync(0xffffffffu, s, 1);
        ss += __shfl_xor_sync(0xffffffffu, ss, 1);
        s  += __shfl_xor_sync(0xffffffffu, s, 2);
        ss += __shfl_xor_sync(0xffffffffu, ss, 2);
        if (part==0){
            float m = s*(1.f/96.f);
            mu[px]=m; rs[px]=rsqrtf(ss*(1.f/96.f)-m*m+1e-6f);
        }
    }
    __syncthreads();
    // normalize in place
    for (int i=threadIdx.x; i<96*64; i+=256){
        int c=i>>6, p=i&63;
        Xs[c*X1S+p] = (Xs[c*X1S+p]-mu[p])*rs[p]*lg[q*96+c] + lb[q*96+c];
    }
    __syncthreads();
    int tp = threadIdx.x & 15, tc = threadIdx.x >> 4;
    unsigned long long acc[6][4];   // [oc-pair][px]
    #pragma unroll
    for (int j=0;j<6;j++){ acc[j][0]=0ull; acc[j][1]=0ull; acc[j][2]=0ull; acc[j][3]=0ull; }
    const float* xbq = Xs + 4*tp;
    const float* wbq = Ws + 12*tc;
    #pragma unroll 2
    for (int k=0;k<96;k++){
        float4 xv = *(const float4*)(xbq + k*X1S);
        unsigned long long xd0 = pack2(xv.x), xd1 = pack2(xv.y),
                           xd2 = pack2(xv.z), xd3 = pack2(xv.w);
        const unsigned long long* wp = (const unsigned long long*)(wbq + k*W1S);
        #pragma unroll
        for (int j=0;j<6;j++){
            unsigned long long wv = wp[j];
            fma2(acc[j][0], wv, xd0);
            fma2(acc[j][1], wv, xd1);
            fma2(acc[j][2], wv, xd2);
            fma2(acc[j][3], wv, xd3);
        }
    }
    __syncthreads();                  // done reading Xs/Ws
    float* sout = sm;                 // [64][100]
    // ---- conv0 (tc 0-7) ----
    if (tc < 8){
        #pragma unroll
        for (int j=0;j<6;j++){
            int oc = 12*tc + 2*j;
            #pragma unroll
            for (int i=0;i<4;i++){
                float2 v = unpack2(acc[j][i]);
                sout[(size_t)(4*tp+i)*100 + oc    ] = v.x;
                sout[(size_t)(4*tp+i)*100 + oc + 1] = v.y;
            }
        }
    }
    __syncthreads();
    {
        float* dst = g_a + ((size_t)q*PXQ + P0)*96;
        for (int i=threadIdx.x; i<64*96; i+=256){
            int p=i/96, oc=i%96;
            dst[i] = siluf(sout[p*100+oc] + b0s[oc]);
        }
    }
    __syncthreads();
    // ---- conv1 (tc 8-15) ----
    if (tc >= 8){
        #pragma unroll
        for (int j=0;j<6;j++){
            int oc = 12*(tc-8) + 2*j;
            #pragma unroll
            for (int i=0;i<4;i++){
                float2 v = unpack2(acc[j][i]);
                sout[(size_t)(4*tp+i)*100 + oc    ] = v.x;
                sout[(size_t)(4*tp+i)*100 + oc + 1] = v.y;
            }
        }
    }
    __syncthreads();
    {
        float* dst = g_zin + ((size_t)q*PXQ + P0)*96;
        for (int i=threadIdx.x; i<64*96; i+=256){
            int p=i/96, oc=i%96;
            dst[i] = sout[p*100+oc] + b1s[oc];
        }
    }
}

// =============== K2: depthwise 3x3 + bias + silu + pre-transform; zeros g_y ===============
__global__ __launch_bounds__(256) void k2_dw(const float* __restrict__ dww, const float* __restrict__ dwb,
                                             const int* __restrict__ bidx)
{
    extern __shared__ float rows[];         // [3][48*96]
    __shared__ float wsm[96*9];
    __shared__ float bsm[96];
    int qb = blockIdx.x, q = qb>>4, hr = blockIdx.y;
    if (blockIdx.x==0 && blockIdx.y==0)
        for (int i=threadIdx.x; i<NBQ*CC; i+=256) g_ysum[i]=0.f;
    {
        float* yz = g_y + ((size_t)qb*LL + hr*48)*96;
        for (int i=threadIdx.x; i<48*96; i+=256) yz[i]=0.f;
    }
    for (int i=threadIdx.x; i<96*9; i+=256) wsm[i]=dww[q*96*9 + i];
    for (int i=threadIdx.x; i<96;   i+=256) bsm[i]=dwb[q*96 + i];
    for (int dy=0; dy<3; dy++){
        int hh = hr-1+dy;
        if (hh>=0 && hh<48){
            const float* src = g_zin + ((size_t)qb*LL + hh*48)*96;
            for (int i=threadIdx.x; i<48*96; i+=256) rows[dy*4608+i]=src[i];
        } else {
            for (int i=threadIdx.x; i<48*96; i+=256) rows[dy*4608+i]=0.f;
        }
    }
    __syncthreads();
    bool even = ((bidx[0] & 1) == 0);
    for (int i=threadIdx.x; i<48*96; i+=256){
        int w=i/96, c=i%96;
        float acc = bsm[c];
        #pragma unroll
        for (int dy=0; dy<3; dy++){
            #pragma unroll
            for (int dx=0; dx<3; dx++){
                int ww = w+dx-1;
                if (ww>=0 && ww<48) acc += wsm[c*9+dy*3+dx]*rows[dy*4608 + ww*96 + c];
            }
        }
        float z = siluf(acc);
        int pf = even ? (w*48+hr) : ((47-hr)*48+(47-w));
        g_vf[((size_t)qb*LL + pf)*96 + c] = z;
    }
}

// =============== K3: x-projection GEMM -> plane layout ===============
// grid (288, 2, 4), block 256 = 32 tp(4px) x 8 tc(6oc via 3 pairs). Tile 128px x 48oc.
#define K3XS 132
#define K3WS 50
__global__ __launch_bounds__(256,3) void k3_proj(const float* __restrict__ xprojw)
{
    extern __shared__ float sm[];
    float* Xs = sm;                // [96][132]
    float* Ws = sm + 96*K3XS;      // [96][50]
    int q = blockIdx.z, src = blockIdx.y, P0 = blockIdx.x*128;
    int b_img = P0 / LL;
    int l0 = P0 % LL;
    const float* vbase = g_vf + (size_t)(q*16 + b_img)*LL*96;
    for (int i=threadIdx.x; i<128*96; i+=256){
        int p=i/96, c=i%96;
        int l = l0 + p;
        int row = src ? ((l%48)*48 + l/48) : l;
        Xs[c*K3XS+p] = vbase[(size_t)row*96 + c];
    }
    for (int i=threadIdx.x; i<48*96; i+=256){
        int oc=i/96, kk=i%96;
        float v=0.f;
        if (oc<44){
            int k = (oc<22)? src : src+2;
            int d = (oc<22)? oc : oc-22;
            v = xprojw[(((size_t)q*4 + k)*22 + d)*96 + kk];
        }
        Ws[kk*K3WS+oc]=v;
    }
    __syncthreads();
    int tp = threadIdx.x & 31, tc = threadIdx.x >> 5;
    unsigned long long acc[3][4];   // [oc-pair][px]
    #pragma unroll
    for (int j=0;j<3;j++){ acc[j][0]=0ull; acc[j][1]=0ull; acc[j][2]=0ull; acc[j][3]=0ull; }
    const float* xbq = Xs + 4*tp;
    const float* wbq = Ws + 6*tc;
    #pragma unroll 4
    for (int k=0;k<96;k++){
        float4 xv = *(const float4*)(xbq + k*K3XS);
        unsigned long long xd0 = pack2(xv.x), xd1 = pack2(xv.y),
                           xd2 = pack2(xv.z), xd3 = pack2(xv.w);
        const unsigned long long* wp = (const unsigned long long*)(wbq + k*K3WS);
        #pragma unroll
        for (int j=0;j<3;j++){
            unsigned long long wv = wp[j];
            fma2(acc[j][0], wv, xd0);
            fma2(acc[j][1], wv, xd1);
            fma2(acc[j][2], wv, xd2);
            fma2(acc[j][3], wv, xd3);
        }
    }
    int qb = q*16 + b_img;
    int lw = l0 + 4*tp;
    #pragma unroll
    for (int j=0;j<3;j++){
        float2 v0 = unpack2(acc[j][0]);
        float2 v1 = unpack2(acc[j][1]);
        float2 v2 = unpack2(acc[j][2]);
        float2 v3 = unpack2(acc[j][3]);
        #pragma unroll
        for (int h=0; h<2; h++){
            int oc = 6*tc + 2*j + h;
            if (oc>=44) continue;
            int kdir = (oc<22)? src : src+2;
            int d    = (oc<22)? oc : oc-22;
            int plane= (d<6)? d : d+2;
            float* dst = g_xdbl + (((size_t)qb*4 + kdir)*NPL + plane)*LL + lw;
            *(float4*)dst = h ? make_float4(v0.y,v1.y,v2.y,v3.y)
                              : make_float4(v0.x,v1.x,v2.x,v3.x);
        }
    }
}

// =============== K-scan: selective scan, atomic-combine into g_y ===============
__global__ __launch_bounds__(96) void k_scan(const float* __restrict__ dtw_g, const float* __restrict__ dtb_g,
                                             const float* __restrict__ alog_g, const float* __restrict__ ds_g)
{
    __shared__ float s_u [2][16*96];
    __shared__ float s_xd[2][NPL*16];
    int qb = blockIdx.x, k = blockIdx.y, q = qb>>4;
    int c = threadIdx.x;
    int pidx = (q*4+k)*96 + c;
    float dtw[6];
    #pragma unroll
    for (int r=0;r<6;r++) dtw[r]=dtw_g[pidx*6+r];
    float dtb = dtb_g[pidx];
    float Ac[8];
    #pragma unroll
    for (int n=0;n<8;n++) Ac[n] = -__expf(alog_g[pidx*8+n]);
    float Dv = ds_g[pidx];
    const float* u_base  = g_vf + (size_t)qb*LL*96;
    const float* xd_base = g_xdbl + ((size_t)qb*4+k)*NPL*LL;
    float* y_base = g_y + (size_t)qb*LL*96;
    bool rev = (k>=2);
    int kt = k & 1;
    int plane = c>>2, piece = c&3;
    float hs[8];
    #pragma unroll
    for (int n=0;n<8;n++) hs[n]=0.f;

    auto load_u = [&](int buf, int sst){
        int a0 = sst/48, b0 = sst%48;
        #pragma unroll
        for (int jj=0;jj<4;jj++){
            int pc = c + 96*jj;
            int off = pc/24, fo = pc%24;
            int row = kt ? ((b0+off)*48 + a0) : (sst+off);
            cpasync16(&s_u[buf][off*96 + fo*4], u_base + (size_t)row*96 + fo*4);
        }
        cpasync16(&s_xd[buf][plane*16 + piece*4], xd_base + (size_t)plane*LL + sst + piece*4);
    };

    {
        int sst = rev ? (LL-16) : 0;
        load_u(0, sst);
        asm volatile("cp.async.commit_group;");
    }
    for (int cs=0; cs<144; cs++){
        if (cs<143){
            int cn = cs+1;
            int sst = rev ? (LL - 16*(cn+1)) : 16*cn;
            load_u(cn & 1, sst);
            asm volatile("cp.async.commit_group;");
            asm volatile("cp.async.wait_group 1;");
        } else {
            asm volatile("cp.async.wait_group 0;");
        }
        __syncthreads();
        int buf = cs & 1;
        int sst = rev ? (LL - 16*(cs+1)) : 16*cs;
        int a0 = sst/48, b0 = sst%48;
        const float* xd = &s_xd[buf][0];
        #pragma unroll 4
        for (int j=0;j<16;j++){
            int off = rev ? (15-j) : j;
            float draw = dtb + dtw[0]*xd[0*16+off] + dtw[1]*xd[1*16+off] + dtw[2]*xd[2*16+off]
                             + dtw[3]*xd[3*16+off] + dtw[4]*xd[4*16+off] + dtw[5]*xd[5*16+off];
            float delta = (draw > 15.f) ? draw : __logf(1.f + __expf(draw));
            float u = s_u[buf][off*96 + c];
            float du = delta*u;
            float y = Dv*u;
            hs[0] = __expf(delta*Ac[0])*hs[0] + du*xd[( 8)*16+off];  y += hs[0]*xd[(16)*16+off];
            hs[1] = __expf(delta*Ac[1])*hs[1] + du*xd[( 9)*16+off];  y += hs[1]*xd[(17)*16+off];
            hs[2] = __expf(delta*Ac[2])*hs[2] + du*xd[(10)*16+off];  y += hs[2]*xd[(18)*16+off];
            hs[3] = __expf(delta*Ac[3])*hs[3] + du*xd[(11)*16+off];  y += hs[3]*xd[(19)*16+off];
            hs[4] = __expf(delta*Ac[4])*hs[4] + du*xd[(12)*16+off];  y += hs[4]*xd[(20)*16+off];
            hs[5] = __expf(delta*Ac[5])*hs[5] + du*xd[(13)*16+off];  y += hs[5]*xd[(21)*16+off];
            hs[6] = __expf(delta*Ac[6])*hs[6] + du*xd[(14)*16+off];  y += hs[6]*xd[(22)*16+off];
            hs[7] = __expf(delta*Ac[7])*hs[7] + du*xd[(15)*16+off];  y += hs[7]*xd[(23)*16+off];
            int row = kt ? ((b0+off)*48 + a0) : (sst+off);
            atomicAdd(&y_base[(size_t)row*96 + c], y);
        }
        __syncthreads();
    }
}

// =============== K4: ssln LN + p2n LN + a*z + ysum (reads combined g_y) ===============
__global__ __launch_bounds__(96) void k4_comb(const float* __restrict__ g1g, const float* __restrict__ b1g,
                                              const float* __restrict__ g2g, const float* __restrict__ b2g,
                                              const int* __restrict__ bidx)
{
    __shared__ float T[48*97];
    __shared__ float mu1[48], rs1[48], mu2[48], rs2[48];
    __shared__ float G1[96], B1[96], G2[96], B2[96];
    int qb = blockIdx.x, q = qb>>4, hr = blockIdx.y, tid = threadIdx.x;
    bool even = ((bidx[0] & 1) == 0);
    G1[tid]=g1g[q*96+tid]; B1[tid]=b1g[q*96+tid];
    G2[tid]=g2g[q*96+tid]; B2[tid]=b2g[q*96+tid];
    const float* yb = g_y + (size_t)qb*LL*96;
    for (int i=tid; i<48*96; i+=96){
        int w=i/96, c=i%96;
        int pf = even ? (w*48+hr) : ((47-hr)*48+(47-w));
        T[w*97+c] = yb[(size_t)pf*96+c];
    }
    __syncthreads();
    {
        int p = tid>>1, half = tid&1;
        float s=0.f, ss=0.f;
        const float* row = &T[p*97 + half*48];
        #pragma unroll 8
        for (int c=0;c<48;c++){ float v=row[c]; s+=v; ss+=v*v; }
        s  += __shfl_xor_sync(0xffffffffu, s, 1);
        ss += __shfl_xor_sync(0xffffffffu, ss, 1);
        if (half==0){
            float m = s*(1.f/96.f);
            mu1[p]=m; rs1[p]=rsqrtf(ss*(1.f/96.f)-m*m+1e-6f);
        }
    }
    __syncthreads();
    {
        int p = tid>>1, half = tid&1;
        float m1=mu1[p], r1=rs1[p];
        float s=0.f, ss=0.f;
        const float* row = &T[p*97 + half*48];
        const float* gg = &G1[half*48];
        const float* bb = &B1[half*48];
        #pragma unroll 8
        for (int c=0;c<48;c++){ float t=(row[c]-m1)*r1*gg[c]+bb[c]; s+=t; ss+=t*t; }
        s  += __shfl_xor_sync(0xffffffffu, s, 1);
        ss += __shfl_xor_sync(0xffffffffu, ss, 1);
        if (half==0){
            float m = s*(1.f/96.f);
            mu2[p]=m; rs2[p]=rsqrtf(ss*(1.f/96.f)-m*m+1e-6f);
        }
    }
    __syncthreads();
    {
        int c = tid;
        float g1=G1[c], b1=B1[c], g2=G2[c], b2=B2[c];
        float ysum=0.f;
        const float* ab = g_a  + ((size_t)qb*LL + hr*48)*96;
        float*       yo = g_yo + ((size_t)qb*LL + hr*48)*96;
        for (int w=0; w<48; w++){
            float o = T[w*97+c];
            float t  = (o-mu1[w])*rs1[w]*g1 + b1;
            float z2 = (t-mu2[w])*rs2[w]*g2 + b2;
            float a = ab[(size_t)w*96 + c];
            float y = a*z2;
            ysum += y;
            yo[(size_t)w*96 + c] = y;
        }
        atomicAdd(&g_ysum[qb*96+c], ysum);
    }
}

// =============== K5: channel attention ===============
__global__ __launch_bounds__(96) void k5_att(const float* __restrict__ w1, const float* __restrict__ b1,
                                             const float* __restrict__ w2, const float* __restrict__ b2)
{
    __shared__ float sv[96], tv[12];
    int qb = blockIdx.x, q = qb>>4, c = threadIdx.x;
    sv[c] = g_ysum[qb*96+c] * (1.f/2304.f);
    __syncthreads();
    if (c<12){
        float acc = b1[q*12+c];
        #pragma unroll 8
        for (int cc=0; cc<96; cc++) acc += w1[(q*12+c)*96+cc]*sv[cc];
        tv[c] = siluf(acc);
    }
    __syncthreads();
    float acc = b2[q*96+c];
    #pragma unroll
    for (int r=0;r<12;r++) acc += w2[(q*96+c)*12+r]*tv[r];
    g_att[qb*96+c] = 1.f/(1.f+__expf(-acc));
}

// =============== K6: residual + att + transpose to NCHW ===============
__global__ __launch_bounds__(256) void k6_fin(const float* __restrict__ x, float* __restrict__ out)
{
    __shared__ float tile[96*49];
    __shared__ float atts[96];
    int qb = blockIdx.x, q = qb>>4, bb = qb&15, hr = blockIdx.y;
    int qh=(q>>1)*48, qw=(q&1)*48;
    const float* src = g_yo + ((size_t)qb*LL + hr*48)*96;
    for (int i=threadIdx.x; i<48*96; i+=256){
        int w=i/96, c=i%96;
        tile[c*49+w] = src[i];
    }
    for (int i=threadIdx.x; i<96; i+=256) atts[i]=g_att[qb*96+i];
    __syncthreads();
    for (int i=threadIdx.x; i<96*48; i+=256){
        int c=i/48, w=i%48;
        size_t oi = ((size_t)(bb*96+c)*96 + qh+hr)*96 + qw + w;
        out[oi] = x[oi] + tile[c*49+w]*atts[c];
    }
}

// ================================================================
extern "C" void kernel_launch(void* const* d_in, const int* in_sizes, int n_in,
                              void* d_out, int out_size)
{
    const float* x    = (const float*)d_in[0];
    const float* ln_g = (const float*)d_in[1];
    const float* ln_b = (const float*)d_in[2];
    const float* p1w  = (const float*)d_in[3];
    const float* p1b  = (const float*)d_in[4];
    const float* p2w  = (const float*)d_in[5];
    const float* p2b  = (const float*)d_in[6];
    const float* dww  = (const float*)d_in[7];
    const float* dwb  = (const float*)d_in[8];
    const float* xprj = (const float*)d_in[9];
    const float* dtw  = (const float*)d_in[10];
    const float* dtb  = (const float*)d_in[11];
    const float* alog = (const float*)d_in[12];
    const float* dsv  = (const float*)d_in[13];
    const float* ssg  = (const float*)d_in[14];
    const float* ssb  = (const float*)d_in[15];
    const float* png  = (const float*)d_in[16];
    const float* pnb  = (const float*)d_in[17];
    const float* cw1  = (const float*)d_in[18];
    const float* cb1  = (const float*)d_in[19];
    const float* cw2  = (const float*)d_in[20];
    const float* cb2  = (const float*)d_in[21];
    const int*   bidx = (const int*)  d_in[22];
    float* out = (float*)d_out;

    const int smem_k1 = (96*X1S + 96*W1S)*4;     // 102144
    const int smem_k2 = 3*48*96*4;               // 55296
    const int smem_k3 = (96*K3XS + 96*K3WS)*4;   // 69888
    cudaFuncSetAttribute(k1_gemm, cudaFuncAttributeMaxDynamicSharedMemorySize, smem_k1);
    cudaFuncSetAttribute(k2_dw,   cudaFuncAttributeMaxDynamicSharedMemorySize, smem_k2);
    cudaFuncSetAttribute(k3_proj, cudaFuncAttributeMaxDynamicSharedMemorySize, smem_k3);

    k1_gemm<<<dim3(576,4), 256, smem_k1>>>(x, ln_g, ln_b, p1w, p1b, p2w, p2b);
    k2_dw  <<<dim3(64,48), 256, smem_k2>>>(dww, dwb, bidx);
    k3_proj<<<dim3(288,2,4), 256, smem_k3>>>(xprj);
    k_scan <<<dim3(64,4), 96>>>(dtw, dtb, alog, dsv);
    k4_comb<<<dim3(64,48), 96>>>(ssg, ssb, png, pnb, bidx);
    k5_att <<<64, 96>>>(cw1, cb1, cw2, cb2);
    k6_fin <<<dim3(64,48), 256>>>(x, out);
}

// round 9
// speedup vs baseline: 1.3133x; 1.0327x over previous
#include <cuda_runtime.h>
#include <cuda_bf16.h>
#include <cstdint>

#define CC   96
#define LL   2304
#define NBQ  64
#define PXQ  36864
#define NPL  24
#define NSEG 8
#define TCH  18              // chunks of 16 per segment (18*16=288)

// ---------------- static scratch ----------------
__device__ float g_a   [NBQ*LL*CC];
__device__ float g_zin [NBQ*LL*CC];
__device__ float g_vf  [NBQ*LL*CC];
__device__ float g_xdbl[NBQ*4*NPL*LL];
__device__ float g_y   [NBQ*LL*CC];
__device__ float g_yo  [NBQ*LL*CC];
__device__ float g_ysum[NBQ*CC];
__device__ float g_att [NBQ*CC];
__device__ float g_sd  [NBQ*4*NSEG*CC];      // per-segment sum of delta
__device__ float g_hfin[NBQ*4*NSEG*CC*8];    // per-segment local final h
__device__ float g_hin [NBQ*4*NSEG*CC*8];    // per-segment incoming h

__device__ __forceinline__ float siluf(float v){ return v * (1.f/(1.f+__expf(-v))); }

__device__ __forceinline__ void fma2(unsigned long long &acc, unsigned long long a, unsigned long long b){
    asm("fma.rn.f32x2 %0,%1,%2,%0;" : "+l"(acc) : "l"(a), "l"(b));
}
__device__ __forceinline__ unsigned long long pack2(float v){
    unsigned long long r; asm("mov.b64 %0,{%1,%1};" : "=l"(r) : "f"(v)); return r;
}
__device__ __forceinline__ float2 unpack2(unsigned long long v){
    float2 r; asm("mov.b64 {%0,%1},%2;" : "=f"(r.x), "=f"(r.y) : "l"(v)); return r;
}
__device__ __forceinline__ void cpasync16(void* dst, const void* src){
    unsigned d = (unsigned)__cvta_generic_to_shared(dst);
    asm volatile("cp.async.ca.shared.global [%0],[%1],16;" :: "r"(d), "l"(src));
}

// =============== K1: LN + BOTH 1x1 convs fused ===============
#define X1S 68
#define W1S 198
__global__ __launch_bounds__(256,2) void k1_gemm(const float* __restrict__ x,
                                                 const float* __restrict__ lg, const float* __restrict__ lb,
                                                 const float* __restrict__ p1w, const float* __restrict__ p1b,
                                                 const float* __restrict__ p2w, const float* __restrict__ p2b)
{
    extern __shared__ float sm[];
    float* Xs = sm;
    float* Ws = sm + 96*X1S;
    __shared__ float mu[64], rs[64];
    __shared__ float b0s[96], b1s[96];
    int q = blockIdx.y, P0 = blockIdx.x*64;
    int bb = P0 / LL, l0 = P0 % LL;
    int qh=(q>>1)*48, qw=(q&1)*48;
    const float* xb = x + (size_t)bb*884736 + (size_t)qh*96 + qw;
    for (int i=threadIdx.x; i<96*64; i+=256){
        int c=i>>6, p=i&63;
        int l=l0+p, h=l/48, w=l%48;
        Xs[c*X1S+p] = xb[(size_t)c*9216 + h*96 + w];
    }
    const float* W0 = p1w + (size_t)q*9216;
    const float* W1 = p2w + (size_t)q*9216;
    for (int i=threadIdx.x; i<9216; i+=256){
        int d=i/96, c=i%96;
        Ws[c*W1S+d]    = W0[i];
        Ws[c*W1S+96+d] = W1[i];
    }
    for (int i=threadIdx.x; i<96; i+=256){ b0s[i]=p1b[q*96+i]; b1s[i]=p2b[q*96+i]; }
    __syncthreads();
    {
        int px = threadIdx.x>>2, part = threadIdx.x&3;
        float s=0.f, ss=0.f;
        const float* col = Xs + px;
        #pragma unroll 8
        for (int cc=part*24; cc<part*24+24; cc++){ float v=col[cc*X1S]; s+=v; ss+=v*v; }
        s  += __shfl_xor_sync(0xffffffffu, s, 1);
        ss += __shfl_xor_sync(0xffffffffu, ss, 1);
        s  += __shfl_xor_sync(0xffffffffu, s, 2);
        ss += __shfl_xor_sync(0xffffffffu, ss, 2);
        if (part==0){
            float m = s*(1.f/96.f);
            mu[px]=m; rs[px]=rsqrtf(ss*(1.f/96.f)-m*m+1e-6f);
        }
    }
    __syncthreads();
    for (int i=threadIdx.x; i<96*64; i+=256){
        int c=i>>6, p=i&63;
        Xs[c*X1S+p] = (Xs[c*X1S+p]-mu[p])*rs[p]*lg[q*96+c] + lb[q*96+c];
    }
    __syncthreads();
    int tp = threadIdx.x & 15, tc = threadIdx.x >> 4;
    unsigned long long acc[6][4];
    #pragma unroll
    for (int j=0;j<6;j++){ acc[j][0]=0ull; acc[j][1]=0ull; acc[j][2]=0ull; acc[j][3]=0ull; }
    const float* xbq = Xs + 4*tp;
    const float* wbq = Ws + 12*tc;
    #pragma unroll 2
    for (int k=0;k<96;k++){
        float4 xv = *(const float4*)(xbq + k*X1S);
        unsigned long long xd0 = pack2(xv.x), xd1 = pack2(xv.y),
                           xd2 = pack2(xv.z), xd3 = pack2(xv.w);
        const unsigned long long* wp = (const unsigned long long*)(wbq + k*W1S);
        #pragma unroll
        for (int j=0;j<6;j++){
            unsigned long long wv = wp[j];
            fma2(acc[j][0], wv, xd0);
            fma2(acc[j][1], wv, xd1);
            fma2(acc[j][2], wv, xd2);
            fma2(acc[j][3], wv, xd3);
        }
    }
    __syncthreads();
    float* sout = sm;                 // [64][100]
    if (tc < 8){
        #pragma unroll
        for (int j=0;j<6;j++){
            int oc = 12*tc + 2*j;
            #pragma unroll
            for (int i=0;i<4;i++){
                float2 v = unpack2(acc[j][i]);
                sout[(size_t)(4*tp+i)*100 + oc    ] = v.x;
                sout[(size_t)(4*tp+i)*100 + oc + 1] = v.y;
            }
        }
    }
    __syncthreads();
    {
        float* dst = g_a + ((size_t)q*PXQ + P0)*96;
        for (int i=threadIdx.x; i<64*96; i+=256){
            int p=i/96, oc=i%96;
            dst[i] = siluf(sout[p*100+oc] + b0s[oc]);
        }
    }
    __syncthreads();
    if (tc >= 8){
        #pragma unroll
        for (int j=0;j<6;j++){
            int oc = 12*(tc-8) + 2*j;
            #pragma unroll
            for (int i=0;i<4;i++){
                float2 v = unpack2(acc[j][i]);
                sout[(size_t)(4*tp+i)*100 + oc    ] = v.x;
                sout[(size_t)(4*tp+i)*100 + oc + 1] = v.y;
            }
        }
    }
    __syncthreads();
    {
        float* dst = g_zin + ((size_t)q*PXQ + P0)*96;
        for (int i=threadIdx.x; i<64*96; i+=256){
            int p=i/96, oc=i%96;
            dst[i] = sout[p*100+oc] + b1s[oc];
        }
    }
}

// =============== K2: depthwise 3x3 + bias + silu + pre-transform; zeros g_y ===============
__global__ __launch_bounds__(256) void k2_dw(const float* __restrict__ dww, const float* __restrict__ dwb,
                                             const int* __restrict__ bidx)
{
    extern __shared__ float rows[];
    __shared__ float wsm[96*9];
    __shared__ float bsm[96];
    int qb = blockIdx.x, q = qb>>4, hr = blockIdx.y;
    if (blockIdx.x==0 && blockIdx.y==0)
        for (int i=threadIdx.x; i<NBQ*CC; i+=256) g_ysum[i]=0.f;
    {
        float* yz = g_y + ((size_t)qb*LL + hr*48)*96;
        for (int i=threadIdx.x; i<48*96; i+=256) yz[i]=0.f;
    }
    for (int i=threadIdx.x; i<96*9; i+=256) wsm[i]=dww[q*96*9 + i];
    for (int i=threadIdx.x; i<96;   i+=256) bsm[i]=dwb[q*96 + i];
    for (int dy=0; dy<3; dy++){
        int hh = hr-1+dy;
        if (hh>=0 && hh<48){
            const float* src = g_zin + ((size_t)qb*LL + hh*48)*96;
            for (int i=threadIdx.x; i<48*96; i+=256) rows[dy*4608+i]=src[i];
        } else {
            for (int i=threadIdx.x; i<48*96; i+=256) rows[dy*4608+i]=0.f;
        }
    }
    __syncthreads();
    bool even = ((bidx[0] & 1) == 0);
    for (int i=threadIdx.x; i<48*96; i+=256){
        int w=i/96, c=i%96;
        float acc = bsm[c];
        #pragma unroll
        for (int dy=0; dy<3; dy++){
            #pragma unroll
            for (int dx=0; dx<3; dx++){
                int ww = w+dx-1;
                if (ww>=0 && ww<48) acc += wsm[c*9+dy*3+dx]*rows[dy*4608 + ww*96 + c];
            }
        }
        float z = siluf(acc);
        int pf = even ? (w*48+hr) : ((47-hr)*48+(47-w));
        g_vf[((size_t)qb*LL + pf)*96 + c] = z;
    }
}

// =============== K3: x-projection GEMM -> plane layout ===============
#define K3XS 132
#define K3WS 50
__global__ __launch_bounds__(256,3) void k3_proj(const float* __restrict__ xprojw)
{
    extern __shared__ float sm[];
    float* Xs = sm;
    float* Ws = sm + 96*K3XS;
    int q = blockIdx.z, src = blockIdx.y, P0 = blockIdx.x*128;
    int b_img = P0 / LL;
    int l0 = P0 % LL;
    const float* vbase = g_vf + (size_t)(q*16 + b_img)*LL*96;
    for (int i=threadIdx.x; i<128*96; i+=256){
        int p=i/96, c=i%96;
        int l = l0 + p;
        int row = src ? ((l%48)*48 + l/48) : l;
        Xs[c*K3XS+p] = vbase[(size_t)row*96 + c];
    }
    for (int i=threadIdx.x; i<48*96; i+=256){
        int oc=i/96, kk=i%96;
        float v=0.f;
        if (oc<44){
            int k = (oc<22)? src : src+2;
            int d = (oc<22)? oc : oc-22;
            v = xprojw[(((size_t)q*4 + k)*22 + d)*96 + kk];
        }
        Ws[kk*K3WS+oc]=v;
    }
    __syncthreads();
    int tp = threadIdx.x & 31, tc = threadIdx.x >> 5;
    unsigned long long acc[3][4];
    #pragma unroll
    for (int j=0;j<3;j++){ acc[j][0]=0ull; acc[j][1]=0ull; acc[j][2]=0ull; acc[j][3]=0ull; }
    const float* xbq = Xs + 4*tp;
    const float* wbq = Ws + 6*tc;
    #pragma unroll 4
    for (int k=0;k<96;k++){
        float4 xv = *(const float4*)(xbq + k*K3XS);
        unsigned long long xd0 = pack2(xv.x), xd1 = pack2(xv.y),
                           xd2 = pack2(xv.z), xd3 = pack2(xv.w);
        const unsigned long long* wp = (const unsigned long long*)(wbq + k*K3WS);
        #pragma unroll
        for (int j=0;j<3;j++){
            unsigned long long wv = wp[j];
            fma2(acc[j][0], wv, xd0);
            fma2(acc[j][1], wv, xd1);
            fma2(acc[j][2], wv, xd2);
            fma2(acc[j][3], wv, xd3);
        }
    }
    int qb = q*16 + b_img;
    int lw = l0 + 4*tp;
    #pragma unroll
    for (int j=0;j<3;j++){
        float2 v0 = unpack2(acc[j][0]);
        float2 v1 = unpack2(acc[j][1]);
        float2 v2 = unpack2(acc[j][2]);
        float2 v3 = unpack2(acc[j][3]);
        #pragma unroll
        for (int h=0; h<2; h++){
            int oc = 6*tc + 2*j + h;
            if (oc>=44) continue;
            int kdir = (oc<22)? src : src+2;
            int d    = (oc<22)? oc : oc-22;
            int plane= (d<6)? d : d+2;
            float* dst = g_xdbl + (((size_t)qb*4 + kdir)*NPL + plane)*LL + lw;
            *(float4*)dst = h ? make_float4(v0.y,v1.y,v2.y,v3.y)
                              : make_float4(v0.x,v1.x,v2.x,v3.x);
        }
    }
}

// =============== Scan pass A: segmented local scan (h0=0) ===============
// grid (64, 4, NSEG), block 96
__global__ __launch_bounds__(96) void k_scan_seg(const float* __restrict__ dtw_g, const float* __restrict__ dtb_g,
                                                 const float* __restrict__ alog_g, const float* __restrict__ ds_g)
{
    __shared__ float s_u [2][16*96];
    __shared__ float s_xd[2][NPL*16];
    int qb = blockIdx.x, k = blockIdx.y, seg = blockIdx.z, q = qb>>4;
    int c = threadIdx.x;
    int pidx = (q*4+k)*96 + c;
    float dtw[6];
    #pragma unroll
    for (int r=0;r<6;r++) dtw[r]=dtw_g[pidx*6+r];
    float dtb = dtb_g[pidx];
    float Ac[8];
    #pragma unroll
    for (int n=0;n<8;n++) Ac[n] = -__expf(alog_g[pidx*8+n]);
    float Dv = ds_g[pidx];
    const float* u_base  = g_vf + (size_t)qb*LL*96;
    const float* xd_base = g_xdbl + ((size_t)qb*4+k)*NPL*LL;
    float* y_base = g_y + (size_t)qb*LL*96;
    bool rev = (k>=2);
    int kt = k & 1;
    int plane = c>>2, piece = c&3;
    float hs[8];
    #pragma unroll
    for (int n=0;n<8;n++) hs[n]=0.f;
    float sd = 0.f;
    int cg0 = seg*TCH;

    auto load_u = [&](int buf, int sst){
        int a0 = sst/48, b0 = sst%48;
        #pragma unroll
        for (int jj=0;jj<4;jj++){
            int pc = c + 96*jj;
            int off = pc/24, fo = pc%24;
            int row = kt ? ((b0+off)*48 + a0) : (sst+off);
            cpasync16(&s_u[buf][off*96 + fo*4], u_base + (size_t)row*96 + fo*4);
        }
        cpasync16(&s_xd[buf][plane*16 + piece*4], xd_base + (size_t)plane*LL + sst + piece*4);
    };

    {
        int cg = cg0;
        int sst = rev ? (LL - 16*(cg+1)) : 16*cg;
        load_u(0, sst);
        asm volatile("cp.async.commit_group;");
    }
    for (int cs=0; cs<TCH; cs++){
        if (cs<TCH-1){
            int cg = cg0+cs+1;
            int sst = rev ? (LL - 16*(cg+1)) : 16*cg;
            load_u((cs+1) & 1, sst);
            asm volatile("cp.async.commit_group;");
            asm volatile("cp.async.wait_group 1;");
        } else {
            asm volatile("cp.async.wait_group 0;");
        }
        __syncthreads();
        int buf = cs & 1;
        int cg = cg0+cs;
        int sst = rev ? (LL - 16*(cg+1)) : 16*cg;
        int a0 = sst/48, b0 = sst%48;
        const float* xd = &s_xd[buf][0];
        #pragma unroll 4
        for (int j=0;j<16;j++){
            int off = rev ? (15-j) : j;
            float draw = dtb + dtw[0]*xd[0*16+off] + dtw[1]*xd[1*16+off] + dtw[2]*xd[2*16+off]
                             + dtw[3]*xd[3*16+off] + dtw[4]*xd[4*16+off] + dtw[5]*xd[5*16+off];
            float delta = (draw > 15.f) ? draw : __logf(1.f + __expf(draw));
            sd += delta;
            float u = s_u[buf][off*96 + c];
            float du = delta*u;
            float y = Dv*u;
            hs[0] = __expf(delta*Ac[0])*hs[0] + du*xd[( 8)*16+off];  y += hs[0]*xd[(16)*16+off];
            hs[1] = __expf(delta*Ac[1])*hs[1] + du*xd[( 9)*16+off];  y += hs[1]*xd[(17)*16+off];
            hs[2] = __expf(delta*Ac[2])*hs[2] + du*xd[(10)*16+off];  y += hs[2]*xd[(18)*16+off];
            hs[3] = __expf(delta*Ac[3])*hs[3] + du*xd[(11)*16+off];  y += hs[3]*xd[(19)*16+off];
            hs[4] = __expf(delta*Ac[4])*hs[4] + du*xd[(12)*16+off];  y += hs[4]*xd[(20)*16+off];
            hs[5] = __expf(delta*Ac[5])*hs[5] + du*xd[(13)*16+off];  y += hs[5]*xd[(21)*16+off];
            hs[6] = __expf(delta*Ac[6])*hs[6] + du*xd[(14)*16+off];  y += hs[6]*xd[(22)*16+off];
            hs[7] = __expf(delta*Ac[7])*hs[7] + du*xd[(15)*16+off];  y += hs[7]*xd[(23)*16+off];
            int row = kt ? ((b0+off)*48 + a0) : (sst+off);
            atomicAdd(&y_base[(size_t)row*96 + c], y);
        }
        __syncthreads();
    }
    size_t sidx = ((((size_t)qb*4+k)*NSEG+seg)*96 + c);
    g_sd[sidx] = sd;
    #pragma unroll
    for (int n=0;n<8;n++) g_hfin[sidx*8+n] = hs[n];
}

// =============== Scan prefix: combine segment summaries ===============
// grid (64,4), block 96
__global__ __launch_bounds__(96) void k_scan_prefix(const float* __restrict__ alog_g)
{
    int qb = blockIdx.x, k = blockIdx.y, q = qb>>4;
    int c = threadIdx.x;
    int pidx = (q*4+k)*96 + c;
    float Ac[8];
    #pragma unroll
    for (int n=0;n<8;n++) Ac[n] = -__expf(alog_g[pidx*8+n]);
    float h[8];
    #pragma unroll
    for (int n=0;n<8;n++) h[n]=0.f;
    for (int s=0; s<NSEG; s++){
        size_t sidx = ((((size_t)qb*4+k)*NSEG+s)*96 + c);
        #pragma unroll
        for (int n=0;n<8;n++) g_hin[sidx*8+n] = h[n];
        float sd = g_sd[sidx];
        #pragma unroll
        for (int n=0;n<8;n++) h[n] = __expf(Ac[n]*sd)*h[n] + g_hfin[sidx*8+n];
    }
}

// =============== Scan pass C: add carry-in corrections (segments 1..NSEG-1) ===============
// grid (64, 4, NSEG-1), block 96
__global__ __launch_bounds__(96) void k_scan_fix(const float* __restrict__ dtw_g, const float* __restrict__ dtb_g,
                                                 const float* __restrict__ alog_g)
{
    __shared__ float s_xd[2][NPL*16];
    int qb = blockIdx.x, k = blockIdx.y, seg = blockIdx.z+1, q = qb>>4;
    int c = threadIdx.x;
    int pidx = (q*4+k)*96 + c;
    float dtw[6];
    #pragma unroll
    for (int r=0;r<6;r++) dtw[r]=dtw_g[pidx*6+r];
    float dtb = dtb_g[pidx];
    float Ac[8];
    #pragma unroll
    for (int n=0;n<8;n++) Ac[n] = -__expf(alog_g[pidx*8+n]);
    float hin[8];
    {
        size_t sidx = ((((size_t)qb*4+k)*NSEG+seg)*96 + c);
        #pragma unroll
        for (int n=0;n<8;n++) hin[n] = g_hin[sidx*8+n];
    }
    const float* xd_base = g_xdbl + ((size_t)qb*4+k)*NPL*LL;
    float* y_base = g_y + (size_t)qb*LL*96;
    bool rev = (k>=2);
    int kt = k & 1;
    int plane = c>>2, piece = c&3;
    float cum = 0.f;
    int cg0 = seg*TCH;

    auto load_xd = [&](int buf, int sst){
        cpasync16(&s_xd[buf][plane*16 + piece*4], xd_base + (size_t)plane*LL + sst + piece*4);
    };
    {
        int cg = cg0;
        int sst = rev ? (LL - 16*(cg+1)) : 16*cg;
        load_xd(0, sst);
        asm volatile("cp.async.commit_group;");
    }
    for (int cs=0; cs<TCH; cs++){
        if (cs<TCH-1){
            int cg = cg0+cs+1;
            int sst = rev ? (LL - 16*(cg+1)) : 16*cg;
            load_xd((cs+1) & 1, sst);
            asm volatile("cp.async.commit_group;");
            asm volatile("cp.async.wait_group 1;");
        } else {
            asm volatile("cp.async.wait_group 0;");
        }
        __syncthreads();
        int buf = cs & 1;
        int cg = cg0+cs;
        int sst = rev ? (LL - 16*(cg+1)) : 16*cg;
        int a0 = sst/48, b0 = sst%48;
        const float* xd = &s_xd[buf][0];
        #pragma unroll 4
        for (int j=0;j<16;j++){
            int off = rev ? (15-j) : j;
            float draw = dtb + dtw[0]*xd[0*16+off] + dtw[1]*xd[1*16+off] + dtw[2]*xd[2*16+off]
                             + dtw[3]*xd[3*16+off] + dtw[4]*xd[4*16+off] + dtw[5]*xd[5*16+off];
            float delta = (draw > 15.f) ? draw : __logf(1.f + __expf(draw));
            cum += delta;
            float y = 0.f;
            y += xd[(16)*16+off] * (__expf(cum*Ac[0])*hin[0]);
            y += xd[(17)*16+off] * (__expf(cum*Ac[1])*hin[1]);
            y += xd[(18)*16+off] * (__expf(cum*Ac[2])*hin[2]);
            y += xd[(19)*16+off] * (__expf(cum*Ac[3])*hin[3]);
            y += xd[(20)*16+off] * (__expf(cum*Ac[4])*hin[4]);
            y += xd[(21)*16+off] * (__expf(cum*Ac[5])*hin[5]);
            y += xd[(22)*16+off] * (__expf(cum*Ac[6])*hin[6]);
            y += xd[(23)*16+off] * (__expf(cum*Ac[7])*hin[7]);
            int row = kt ? ((b0+off)*48 + a0) : (sst+off);
            atomicAdd(&y_base[(size_t)row*96 + c], y);
        }
        __syncthreads();
    }
}

// =============== K4: ssln LN + p2n LN + a*z + ysum ===============
__global__ __launch_bounds__(96) void k4_comb(const float* __restrict__ g1g, const float* __restrict__ b1g,
                                              const float* __restrict__ g2g, const float* __restrict__ b2g,
                                              const int* __restrict__ bidx)
{
    __shared__ float T[48*97];
    __shared__ float mu1[48], rs1[48], mu2[48], rs2[48];
    __shared__ float G1[96], B1[96], G2[96], B2[96];
    int qb = blockIdx.x, q = qb>>4, hr = blockIdx.y, tid = threadIdx.x;
    bool even = ((bidx[0] & 1) == 0);
    G1[tid]=g1g[q*96+tid]; B1[tid]=b1g[q*96+tid];
    G2[tid]=g2g[q*96+tid]; B2[tid]=b2g[q*96+tid];
    const float* yb = g_y + (size_t)qb*LL*96;
    for (int i=tid; i<48*96; i+=96){
        int w=i/96, c=i%96;
        int pf = even ? (w*48+hr) : ((47-hr)*48+(47-w));
        T[w*97+c] = yb[(size_t)pf*96+c];
    }
    __syncthreads();
    {
        int p = tid>>1, half = tid&1;
        float s=0.f, ss=0.f;
        const float* row = &T[p*97 + half*48];
        #pragma unroll 8
        for (int c=0;c<48;c++){ float v=row[c]; s+=v; ss+=v*v; }
        s  += __shfl_xor_sync(0xffffffffu, s, 1);
        ss += __shfl_xor_sync(0xffffffffu, ss, 1);
        if (half==0){
            float m = s*(1.f/96.f);
            mu1[p]=m; rs1[p]=rsqrtf(ss*(1.f/96.f)-m*m+1e-6f);
        }
    }
    __syncthreads();
    {
        int p = tid>>1, half = tid&1;
        float m1=mu1[p], r1=rs1[p];
        float s=0.f, ss=0.f;
        const float* row = &T[p*97 + half*48];
        const float* gg = &G1[half*48];
        const float* bb = &B1[half*48];
        #pragma unroll 8
        for (int c=0;c<48;c++){ float t=(row[c]-m1)*r1*gg[c]+bb[c]; s+=t; ss+=t*t; }
        s  += __shfl_xor_sync(0xffffffffu, s, 1);
        ss += __shfl_xor_sync(0xffffffffu, ss, 1);
        if (half==0){
            float m = s*(1.f/96.f);
            mu2[p]=m; rs2[p]=rsqrtf(ss*(1.f/96.f)-m*m+1e-6f);
        }
    }
    __syncthreads();
    {
        int c = tid;
        float g1=G1[c], b1=B1[c], g2=G2[c], b2=B2[c];
        float ysum=0.f;
        const float* ab = g_a  + ((size_t)qb*LL + hr*48)*96;
        float*       yo = g_yo + ((size_t)qb*LL + hr*48)*96;
        for (int w=0; w<48; w++){
            float o = T[w*97+c];
            float t  = (o-mu1[w])*rs1[w]*g1 + b1;
            float z2 = (t-mu2[w])*rs2[w]*g2 + b2;
            float a = ab[(size_t)w*96 + c];
            float y = a*z2;
            ysum += y;
            yo[(size_t)w*96 + c] = y;
        }
        atomicAdd(&g_ysum[qb*96+c], ysum);
    }
}

// =============== K5: channel attention ===============
__global__ __launch_bounds__(96) void k5_att(const float* __restrict__ w1, const float* __restrict__ b1,
                                             const float* __restrict__ w2, const float* __restrict__ b2)
{
    __shared__ float sv[96], tv[12];
    int qb = blockIdx.x, q = qb>>4, c = threadIdx.x;
    sv[c] = g_ysum[qb*96+c] * (1.f/2304.f);
    __syncthreads();
    if (c<12){
        float acc = b1[q*12+c];
        #pragma unroll 8
        for (int cc=0; cc<96; cc++) acc += w1[(q*12+c)*96+cc]*sv[cc];
        tv[c] = siluf(acc);
    }
    __syncthreads();
    float acc = b2[q*96+c];
    #pragma unroll
    for (int r=0;r<12;r++) acc += w2[(q*96+c)*12+r]*tv[r];
    g_att[qb*96+c] = 1.f/(1.f+__expf(-acc));
}

// =============== K6: residual + att + transpose to NCHW ===============
__global__ __launch_bounds__(256) void k6_fin(const float* __restrict__ x, float* __restrict__ out)
{
    __shared__ float tile[96*49];
    __shared__ float atts[96];
    int qb = blockIdx.x, q = qb>>4, bb = qb&15, hr = blockIdx.y;
    int qh=(q>>1)*48, qw=(q&1)*48;
    const float* src = g_yo + ((size_t)qb*LL + hr*48)*96;
    for (int i=threadIdx.x; i<48*96; i+=256){
        int w=i/96, c=i%96;
        tile[c*49+w] = src[i];
    }
    for (int i=threadIdx.x; i<96; i+=256) atts[i]=g_att[qb*96+i];
    __syncthreads();
    for (int i=threadIdx.x; i<96*48; i+=256){
        int c=i/48, w=i%48;
        size_t oi = ((size_t)(bb*96+c)*96 + qh+hr)*96 + qw + w;
        out[oi] = x[oi] + tile[c*49+w]*atts[c];
    }
}

// ================================================================
extern "C" void kernel_launch(void* const* d_in, const int* in_sizes, int n_in,
                              void* d_out, int out_size)
{
    const float* x    = (const float*)d_in[0];
    const float* ln_g = (const float*)d_in[1];
    const float* ln_b = (const float*)d_in[2];
    const float* p1w  = (const float*)d_in[3];
    const float* p1b  = (const float*)d_in[4];
    const float* p2w  = (const float*)d_in[5];
    const float* p2b  = (const float*)d_in[6];
    const float* dww  = (const float*)d_in[7];
    const float* dwb  = (const float*)d_in[8];
    const float* xprj = (const float*)d_in[9];
    const float* dtw  = (const float*)d_in[10];
    const float* dtb  = (const float*)d_in[11];
    const float* alog = (const float*)d_in[12];
    const float* dsv  = (const float*)d_in[13];
    const float* ssg  = (const float*)d_in[14];
    const float* ssb  = (const float*)d_in[15];
    const float* png  = (const float*)d_in[16];
    const float* pnb  = (const float*)d_in[17];
    const float* cw1  = (const float*)d_in[18];
    const float* cb1  = (const float*)d_in[19];
    const float* cw2  = (const float*)d_in[20];
    const float* cb2  = (const float*)d_in[21];
    const int*   bidx = (const int*)  d_in[22];
    float* out = (float*)d_out;

    const int smem_k1 = (96*X1S + 96*W1S)*4;
    const int smem_k2 = 3*48*96*4;
    const int smem_k3 = (96*K3XS + 96*K3WS)*4;
    cudaFuncSetAttribute(k1_gemm, cudaFuncAttributeMaxDynamicSharedMemorySize, smem_k1);
    cudaFuncSetAttribute(k2_dw,   cudaFuncAttributeMaxDynamicSharedMemorySize, smem_k2);
    cudaFuncSetAttribute(k3_proj, cudaFuncAttributeMaxDynamicSharedMemorySize, smem_k3);

    k1_gemm<<<dim3(576,4), 256, smem_k1>>>(x, ln_g, ln_b, p1w, p1b, p2w, p2b);
    k2_dw  <<<dim3(64,48), 256, smem_k2>>>(dww, dwb, bidx);
    k3_proj<<<dim3(288,2,4), 256, smem_k3>>>(xprj);
    k_scan_seg   <<<dim3(64,4,NSEG), 96>>>(dtw, dtb, alog, dsv);
    k_scan_prefix<<<dim3(64,4), 96>>>(alog);
    k_scan_fix   <<<dim3(64,4,NSEG-1), 96>>>(dtw, dtb, alog);
    k4_comb<<<dim3(64,48), 96>>>(ssg, ssb, png, pnb, bidx);
    k5_att <<<64, 96>>>(cw1, cb1, cw2, cb2);
    k6_fin <<<dim3(64,48), 256>>>(x, out);
}